// round 14
// baseline (speedup 1.0000x reference)
#include <cuda_runtime.h>
#include <cuda_bf16.h>
#include <math.h>
#include <stdint.h>

// Problem constants
#define BB 2
#define CC 48
#define HH 64
#define WW 64
#define NN 4096
#define RPE_S 191
#define NSPLIT 4
#define KEYS_PER_SPLIT (NN / NSPLIT)

#define RP_ROWS 194
#define RP_STRIDE 196

// ---------------- scratch (device globals; no allocation allowed) -------------
__device__ float  g_q  [BB*CC*NN];       // [c][m] (deform needs this layout)
__device__ float  g_qt [BB*NN*CC];       // [m][c] transposed for attn fills
__device__ float  g_kt [BB*NN*CC];       // [n][c]
__device__ float  g_x2 [BB*96*NN];
__device__ float  g_pos[BB*NN*2];
__device__ float  g_xs [BB*CC*NN];
__device__ float  g_v  [BB*CC*NN];       // [c][n]
__device__ float  g_win[BB*CC*NN];
__device__ float  g_opart[NSPLIT*BB*CC*NN];
__device__ float  g_mpart[NSPLIT*BB*NN];
__device__ float  g_lpart[NSPLIT*BB*NN];
__device__ float4 g_rpe4[RP_ROWS*RP_STRIDE];

// ---------------- MMA helpers -----------------------------------------------------
__device__ __forceinline__ uint32_t f2tf(float f) {
    uint32_t r; asm("cvt.rna.tf32.f32 %0, %1;" : "=r"(r) : "f"(f)); return r;
}
__device__ __forceinline__ void mma_tf32(float* c,
                                         uint32_t a0, uint32_t a1, uint32_t a2, uint32_t a3,
                                         uint32_t b0, uint32_t b1) {
    asm("mma.sync.aligned.m16n8k8.row.col.f32.tf32.tf32.f32 "
        "{%0,%1,%2,%3}, {%4,%5,%6,%7}, {%8,%9}, {%0,%1,%2,%3};"
        : "+f"(c[0]), "+f"(c[1]), "+f"(c[2]), "+f"(c[3])
        : "r"(a0), "r"(a1), "r"(a2), "r"(a3), "r"(b0), "r"(b1));
}
__device__ __forceinline__ void mma_bf16(float* c,
                                         uint32_t a0, uint32_t a1, uint32_t a2, uint32_t a3,
                                         uint32_t b0, uint32_t b1) {
    asm("mma.sync.aligned.m16n8k16.row.col.f32.bf16.bf16.f32 "
        "{%0,%1,%2,%3}, {%4,%5,%6,%7}, {%8,%9}, {%0,%1,%2,%3};"
        : "+f"(c[0]), "+f"(c[1]), "+f"(c[2]), "+f"(c[3])
        : "r"(a0), "r"(a1), "r"(a2), "r"(a3), "r"(b0), "r"(b1));
}
__device__ __forceinline__ uint32_t packbf(float lo, float hi) {
    __nv_bfloat162 h = __floats2bfloat162_rn(lo, hi);
    return *(uint32_t*)&h;
}

// ---------------- shared 48x48 GEMM tile (128 pixels per block) -------------------
struct ConvSmem {
    float Xs[128 * 52];
    float Ws[48 * 64];
    float bias_s[48];
    float sc_s[48];
};

__device__ __forceinline__ void conv_fill(ConvSmem& S, const float* __restrict__ srcb,
                                          int m0, const float* __restrict__ W, int tid) {
    for (int i = tid; i < CC * 128; i += 256) {
        int c = i >> 7, m = i & 127;
        S.Xs[m * 52 + c] = __uint_as_float(f2tf(srcb[c * NN + m0 + m]));
    }
    for (int i = tid; i < 48 * 64; i += 256) {
        int c = i >> 6, o = i & 63;
        float v = (o < 48) ? W[o * CC + c] * S.sc_s[o] : 0.f;
        S.Ws[c * 64 + (o ^ ((c & 3) << 3))] = __uint_as_float(f2tf(v));
    }
}

__device__ __forceinline__ void conv_mma(const ConvSmem& S, float cS[6][4],
                                         int qrow, int tig, int gid) {
    const uint32_t* Xu = (const uint32_t*)S.Xs;
    const uint32_t* Wu = (const uint32_t*)S.Ws;
#pragma unroll
    for (int nb = 0; nb < 6; nb++) {
        int col = nb * 8 + 2 * tig;
        cS[nb][0] = cS[nb][2] = S.bias_s[col];
        cS[nb][1] = cS[nb][3] = S.bias_s[col + 1];
    }
    const int sw = tig << 3;
#pragma unroll
    for (int kb = 0; kb < 6; kb++) {
        uint32_t a0 = Xu[qrow * 52 + kb * 8 + tig];
        uint32_t a1 = Xu[(qrow + 8) * 52 + kb * 8 + tig];
        uint32_t a2 = Xu[qrow * 52 + kb * 8 + tig + 4];
        uint32_t a3 = Xu[(qrow + 8) * 52 + kb * 8 + tig + 4];
#pragma unroll
        for (int nb = 0; nb < 6; nb++) {
            uint32_t b0 = Wu[(kb * 8 + tig) * 64 + ((nb * 8 + gid) ^ sw)];
            uint32_t b1 = Wu[(kb * 8 + tig + 4) * 64 + ((nb * 8 + gid) ^ sw)];
            mma_tf32(cS[nb], a0, a1, a2, a3, b0, b1);
        }
    }
}

// ---------------- stage1: q + x2(BN) projections + rpe quad-pack -----------------
__global__ void __launch_bounds__(256, 2) stage1_kernel(
    const float* __restrict__ x,
    const float* __restrict__ Wq, const float* __restrict__ bq,
    const float* __restrict__ inp_w, const float* __restrict__ inp_b,
    const float* __restrict__ bng, const float* __restrict__ bnb,
    const float* __restrict__ bnm, const float* __restrict__ bnv,
    const float* __restrict__ rpe) {
    const int tid = threadIdx.x;
    if (blockIdx.y == 6) {
        for (int idx = blockIdx.x * 256 + tid; idx < RP_ROWS * RP_STRIDE; idx += 32 * 256) {
            int r  = idx / RP_STRIDE;
            int xc = idx - r * RP_STRIDE;
            int yy = r - 2, xx = xc - 2;
            float v00 = 0.f, v10 = 0.f, v01 = 0.f, v11 = 0.f;
            bool y0ok = (yy     >= 0 && yy     <= 190);
            bool y1ok = (yy + 1 >= 0 && yy + 1 <= 190);
            if (xx >= 0 && xx <= 190) {
                if (y0ok) v00 = rpe[yy * RPE_S + xx];
                if (y1ok) v10 = rpe[(yy + 1) * RPE_S + xx];
            }
            if (xx + 1 >= 0 && xx + 1 <= 190) {
                if (y0ok) v01 = rpe[yy * RPE_S + xx + 1];
                if (y1ok) v11 = rpe[(yy + 1) * RPE_S + xx + 1];
            }
            g_rpe4[idx] = make_float4(v00, v10, v01, v11);
        }
        return;
    }
    __shared__ ConvSmem S;
    const int job = blockIdx.y >> 1;
    const int b   = blockIdx.y & 1;
    const int m0  = blockIdx.x * 128;

    const float* W;
    const float* bi;
    const float* srcb = x + b * CC * NN;
    float* dstb;
    int bnoff = -1;
    if (job == 0)      { W = Wq;              bi = bq;          dstb = g_q  + b * CC * NN; }
    else if (job == 1) { W = inp_w;           bi = inp_b;       dstb = g_x2 + b * 96 * NN;            bnoff = 0;  }
    else               { W = inp_w + 48 * CC; bi = inp_b + 48;  dstb = g_x2 + (b * 96 + 48) * NN;     bnoff = 48; }

    if (tid < 48) {
        if (bnoff < 0) { S.sc_s[tid] = 1.f; S.bias_s[tid] = bi[tid]; }
        else {
            float sc = rsqrtf(bnv[bnoff + tid] + 1e-5f) * bng[bnoff + tid];
            S.sc_s[tid]   = sc;
            S.bias_s[tid] = (bi[tid] - bnm[bnoff + tid]) * sc + bnb[bnoff + tid];
        }
    }
    __syncthreads();
    conv_fill(S, srcb, m0, W, tid);
    __syncthreads();

    const int warp = tid >> 5, lane = tid & 31;
    const int gid = lane >> 2, tig = lane & 3;
    const int qrow = warp * 16 + gid;
    float cS[6][4];
    conv_mma(S, cS, qrow, tig, gid);

#pragma unroll
    for (int nb = 0; nb < 6; nb++) {
        int col = nb * 8 + 2 * tig;
        dstb[col * NN + m0 + qrow]           = cS[nb][0];
        dstb[(col + 1) * NN + m0 + qrow]     = cS[nb][1];
        dstb[col * NN + m0 + qrow + 8]       = cS[nb][2];
        dstb[(col + 1) * NN + m0 + qrow + 8] = cS[nb][3];
    }
    if (job == 0) {
        float* qt = g_qt + (size_t)b * NN * CC;
#pragma unroll
        for (int nb = 0; nb < 6; nb++) {
            int col = nb * 8 + 2 * tig;
            qt[(m0 + qrow) * CC + col]           = cS[nb][0];
            qt[(m0 + qrow) * CC + col + 1]       = cS[nb][1];
            qt[(m0 + qrow + 8) * CC + col]       = cS[nb][2];
            qt[(m0 + qrow + 8) * CC + col + 1]   = cS[nb][3];
        }
    }
}

// ---------------- stage2: k (transposed), v projections ---------------------------
__global__ void __launch_bounds__(256, 2) stage2_kernel(
    const float* __restrict__ Wk, const float* __restrict__ bk,
    const float* __restrict__ Wv, const float* __restrict__ bv) {
    __shared__ ConvSmem S;
    const int tid = threadIdx.x;
    const int job = blockIdx.y >> 1;
    const int b   = blockIdx.y & 1;
    const int m0  = blockIdx.x * 128;
    const float* W  = job ? Wv : Wk;
    const float* bi = job ? bv : bk;
    const float* srcb = g_xs + b * CC * NN;

    if (tid < 48) { S.sc_s[tid] = 1.f; S.bias_s[tid] = bi[tid]; }
    __syncthreads();
    conv_fill(S, srcb, m0, W, tid);
    __syncthreads();

    const int warp = tid >> 5, lane = tid & 31;
    const int gid = lane >> 2, tig = lane & 3;
    const int qrow = warp * 16 + gid;
    float cS[6][4];
    conv_mma(S, cS, qrow, tig, gid);

    if (job) {
        float* dstb = g_v + b * CC * NN;
#pragma unroll
        for (int nb = 0; nb < 6; nb++) {
            int col = nb * 8 + 2 * tig;
            dstb[col * NN + m0 + qrow]           = cS[nb][0];
            dstb[(col + 1) * NN + m0 + qrow]     = cS[nb][1];
            dstb[col * NN + m0 + qrow + 8]       = cS[nb][2];
            dstb[(col + 1) * NN + m0 + qrow + 8] = cS[nb][3];
        }
    } else {
        float* kt = g_kt + (size_t)b * NN * CC;
#pragma unroll
        for (int nb = 0; nb < 6; nb++) {
            int col = nb * 8 + 2 * tig;
            kt[(m0 + qrow) * CC + col]         = cS[nb][0];
            kt[(m0 + qrow) * CC + col + 1]     = cS[nb][1];
            kt[(m0 + qrow + 8) * CC + col]     = cS[nb][2];
            kt[(m0 + qrow + 8) * CC + col + 1] = cS[nb][3];
        }
    }
}

// ---------------- offset head + position + grid-sample x (512 thr) --------------
__global__ void deform_kernel(const float* __restrict__ x,
                              const float* __restrict__ dww, const float* __restrict__ dwb,
                              const float* __restrict__ lng, const float* __restrict__ lnb,
                              const float* __restrict__ pww) {
    int b = blockIdx.y;
    int y = blockIdx.x;
    int tid = threadIdx.x;
    __shared__ float ts[CC * WW];
    __shared__ float posr[WW * 2];
    __shared__ float redA[8][WW];
    __shared__ float redB[8][WW];

    for (int i = tid; i < CC * WW; i += 512) {
        int c = i >> 6, px = i & 63;
        float acc = dwb[c];
        const float* qc = g_q + (b * CC + c) * NN;
        const float* wc = dww + c * 9;
#pragma unroll
        for (int ky = 0; ky < 3; ky++) {
            int yy = y + ky - 1;
            if (yy < 0 || yy > 63) continue;
#pragma unroll
            for (int kx = 0; kx < 3; kx++) {
                int xx = px + kx - 1;
                if (xx < 0 || xx > 63) continue;
                acc += qc[(yy << 6) + xx] * wc[ky * 3 + kx];
            }
        }
        ts[c * 64 + px] = acc;
    }
    __syncthreads();

    const int sub = tid >> 6;
    const int px  = tid & 63;
    {
        float s = 0.f;
#pragma unroll
        for (int j = 0; j < 6; j++) s += ts[(sub * 6 + j) * 64 + px];
        redA[sub][px] = s;
    }
    __syncthreads();
    float mu = 0.f;
#pragma unroll
    for (int u = 0; u < 8; u++) mu += redA[u][px];
    mu *= (1.f / 48.f);
    {
        float v2 = 0.f;
#pragma unroll
        for (int j = 0; j < 6; j++) {
            float d = ts[(sub * 6 + j) * 64 + px] - mu;
            v2 += d * d;
        }
        redB[sub][px] = v2;
    }
    __syncthreads();
    float var = 0.f;
#pragma unroll
    for (int u = 0; u < 8; u++) var += redB[u][px];
    float rs = rsqrtf(var * (1.f / 48.f) + 1e-5f);
    {
        float a0 = 0.f, a1 = 0.f;
#pragma unroll
        for (int j = 0; j < 6; j++) {
            int c = sub * 6 + j;
            float v = (ts[c * 64 + px] - mu) * rs * lng[c] + lnb[c];
            v = 0.5f * v * (1.f + erff(v * 0.7071067811865475f));
            a0 += pww[c] * v;
            a1 += pww[CC + c] * v;
        }
        redA[sub][px] = a0;
        redB[sub][px] = a1;
    }
    __syncthreads();
    if (tid < WW) {
        float a0 = 0.f, a1 = 0.f;
#pragma unroll
        for (int u = 0; u < 8; u++) { a0 += redA[u][px]; a1 += redB[u][px]; }
        float py  = tanhf(a0) * (2.f / 63.f) + ((0.5f + (float)y ) * (2.f / 63.f) - 1.f);
        float pxx = tanhf(a1) * (2.f / 63.f) + ((0.5f + (float)px) * (2.f / 63.f) - 1.f);
        posr[px * 2 + 0] = py;
        posr[px * 2 + 1] = pxx;
        int n = (y << 6) + px;
        g_pos[(b * NN + n) * 2 + 0] = py;
        g_pos[(b * NN + n) * 2 + 1] = pxx;
    }
    __syncthreads();

    for (int i = tid; i < CC * WW; i += 512) {
        int c = i >> 6, p = i & 63;
        float py  = posr[p * 2 + 0];
        float pxx = posr[p * 2 + 1];
        float gx = (pxx + 1.f) * 0.5f * 63.f;
        float gy = (py  + 1.f) * 0.5f * 63.f;
        const float* img = x + (b * CC + c) * NN;
        float x0f = floorf(gx), y0f = floorf(gy);
        int   x0 = (int)x0f, y0 = (int)y0f;
        float wx = gx - x0f, wy = gy - y0f;
        float acc = 0.f;
#pragma unroll
        for (int dy = 0; dy < 2; dy++) {
            int yc = y0 + dy;
            if (yc < 0 || yc >= HH) continue;
            float wyv = dy ? wy : (1.f - wy);
#pragma unroll
            for (int dx = 0; dx < 2; dx++) {
                int xc = x0 + dx;
                if (xc < 0 || xc >= WW) continue;
                float wxv = dx ? wx : (1.f - wx);
                acc += img[yc * WW + xc] * (wyv * wxv);
            }
        }
        g_xs[(b * CC + c) * NN + (y << 6) + p] = acc;
    }
}

// ---------------- fused flash attention: full bf16 MMA ----------------------------
// smem (u32/f32 units): Qp 128x28, Kp 64x28, Vp 48x36, Pp 128x36, Bs 128x66.
// Q/K packed bf16x2 along channels (stride 28 -> conflict-free frags);
// V/P packed bf16x2 along keys (stride 36 -> conflict-free frags).
#define AOF_QP 0
#define AOF_KP (AOF_QP + 128*28)
#define AOF_VP (AOF_KP + 64*28)
#define AOF_PP (AOF_VP + 48*36)
#define AOF_BS (AOF_PP + 128*36)
#define ATTN_SMEM_FLOATS (AOF_BS + 128*66)
#define ATTN_SMEM_BYTES (ATTN_SMEM_FLOATS * 4)

__global__ void __launch_bounds__(256, 2) attn_kernel() {
    extern __shared__ float sm[];
    uint32_t* Qp = (uint32_t*)(sm + AOF_QP);
    uint32_t* Kp = (uint32_t*)(sm + AOF_KP);
    uint32_t* Vp = (uint32_t*)(sm + AOF_VP);
    uint32_t* Pp = (uint32_t*)(sm + AOF_PP);
    float*    Bs = sm + AOF_BS;

    const int yb    = blockIdx.x;
    const int split = blockIdx.y;
    const int b     = blockIdx.z;
    const int tid   = threadIdx.x;
    const int warp  = tid >> 5;
    const int lane  = tid & 31;
    const int gid   = lane >> 2;
    const int tig   = lane & 3;
    const int m0    = yb * 128;
    const int qrow  = warp * 16 + gid;

    const float scale = 0.14433756729740643f;
    const float step  = 95.0f / 63.0f;

    // load Q tile packed: Qp[m][ci], ci = c/2 (24 words), scaled bf16
    {
        const float* qt = g_qt + (size_t)b * NN * CC;
        for (int i = tid; i < 128 * 24; i += 256) {
            int m = i / 24, ci = i - m * 24;
            float2 q2 = *(const float2*)&qt[(m0 + m) * CC + 2 * ci];
            Qp[m * 28 + ci] = packbf(q2.x * scale, q2.y * scale);
        }
    }

    float rmax0 = -1e30f, rmax1 = -1e30f, rsum0 = 0.f, rsum1 = 0.f;
    float o[6][4];
#pragma unroll
    for (int nb = 0; nb < 6; nb++)
#pragma unroll
        for (int j = 0; j < 4; j++) o[nb][j] = 0.f;

    const int nbase = split * KEYS_PER_SPLIT;
    for (int t = 0; t < KEYS_PER_SPLIT / 64; t++) {
        const int n0 = nbase + t * 64;
        __syncthreads();      // prev tile done with Kp/Vp/Bs

        // K tile packed: Kp[n][ci] from g_kt
        {
            const float* kt = g_kt + (size_t)b * NN * CC;
            for (int i = tid; i < 64 * 24; i += 256) {
                int n = i / 24, ci = i - n * 24;
                float2 k2 = *(const float2*)&kt[(n0 + n) * CC + 2 * ci];
                Kp[n * 28 + ci] = packbf(k2.x, k2.y);
            }
        }
        // V tile packed bf16 pairs along n: Vp[c][pi]
        for (int i = tid; i < 48 * 32; i += 256) {
            int c = i >> 5, pi = i & 31;
            float2 v2 = *(const float2*)&g_v[(b * CC + c) * NN + n0 + 2 * pi];
            Vp[c * 36 + pi] = packbf(v2.x, v2.y);
        }

        // bias -> Bs[m][n] (stride 66)
#pragma unroll
        for (int kk = 0; kk < 8; kk++) {
            int n = warp * 8 + kk;
            float py = g_pos[(b * NN + n0 + n) * 2 + 0];
            float px = g_pos[(b * NN + n0 + n) * 2 + 1];
            float kbx = 47.5f * px;
            float fy[2];
            const float4* row[2];
#pragma unroll
            for (int r = 0; r < 2; r++) {
                float gy = 47.5f + (float)(yb * 2 + r) * step - 47.5f * py;
                float yf = floorf(gy);
                int   iy = (int)yf;
                fy[r] = gy - yf;
                iy = min(max(iy, -2), 191);
                row[r] = g_rpe4 + (iy + 2) * RP_STRIDE;
            }
#pragma unroll
            for (int it = 0; it < 4; it++) {
                int m = it * 32 + lane;
                int r = it >> 1;
                float gx = 47.5f + (float)(m & 63) * step - kbx;
                float xf = floorf(gx);
                float fx = gx - xf;
                int   xi = (int)xf;
                xi = min(max(xi, -2), 192);
                float4 q4 = row[r][xi + 2];
                float b0 = fmaf(fx, q4.z - q4.x, q4.x);
                float b1 = fmaf(fx, q4.w - q4.y, q4.y);
                Bs[m * 66 + n] = fmaf(fy[r], b1 - b0, b0);
            }
        }
        __syncthreads();      // Kp, Vp, Bs complete

        // ---- S = QK^T + bias : C init from Bs, bf16 m16n8k16, 3 k-chunks ----
        float cS[8][4];
#pragma unroll
        for (int nb = 0; nb < 8; nb++) {
            int col = nb * 8 + 2 * tig;
            float2 bA = *(const float2*)&Bs[qrow * 66 + col];
            float2 bB = *(const float2*)&Bs[(qrow + 8) * 66 + col];
            cS[nb][0] = bA.x; cS[nb][1] = bA.y;
            cS[nb][2] = bB.x; cS[nb][3] = bB.y;
        }
#pragma unroll
        for (int kb = 0; kb < 3; kb++) {
            uint32_t a0 = Qp[qrow * 28 + kb * 8 + tig];
            uint32_t a1 = Qp[(qrow + 8) * 28 + kb * 8 + tig];
            uint32_t a2 = Qp[qrow * 28 + kb * 8 + tig + 4];
            uint32_t a3 = Qp[(qrow + 8) * 28 + kb * 8 + tig + 4];
#pragma unroll
            for (int nb = 0; nb < 8; nb++) {
                uint32_t b0 = Kp[(nb * 8 + gid) * 28 + kb * 8 + tig];
                uint32_t b1 = Kp[(nb * 8 + gid) * 28 + kb * 8 + tig + 4];
                mma_bf16(cS[nb], a0, a1, a2, a3, b0, b1);
            }
        }

        // ---- online softmax ----
        float tmax0 = -1e30f, tmax1 = -1e30f;
#pragma unroll
        for (int nb = 0; nb < 8; nb++) {
            tmax0 = fmaxf(tmax0, fmaxf(cS[nb][0], cS[nb][1]));
            tmax1 = fmaxf(tmax1, fmaxf(cS[nb][2], cS[nb][3]));
        }
        tmax0 = fmaxf(tmax0, __shfl_xor_sync(0xffffffffu, tmax0, 1));
        tmax0 = fmaxf(tmax0, __shfl_xor_sync(0xffffffffu, tmax0, 2));
        tmax1 = fmaxf(tmax1, __shfl_xor_sync(0xffffffffu, tmax1, 1));
        tmax1 = fmaxf(tmax1, __shfl_xor_sync(0xffffffffu, tmax1, 2));
        float nmax0 = fmaxf(rmax0, tmax0);
        float nmax1 = fmaxf(rmax1, tmax1);
        float f0 = __expf(rmax0 - nmax0);
        float f1 = __expf(rmax1 - nmax1);
        rmax0 = nmax0; rmax1 = nmax1;

        float psum0 = 0.f, psum1 = 0.f;
#pragma unroll
        for (int nb = 0; nb < 8; nb++) {
            float p0 = __expf(cS[nb][0] - nmax0);
            float p1 = __expf(cS[nb][1] - nmax0);
            float p2 = __expf(cS[nb][2] - nmax1);
            float p3 = __expf(cS[nb][3] - nmax1);
            psum0 += p0 + p1;
            psum1 += p2 + p3;
            Pp[qrow * 36 + nb * 4 + tig]       = packbf(p0, p1);
            Pp[(qrow + 8) * 36 + nb * 4 + tig] = packbf(p2, p3);
        }
        psum0 += __shfl_xor_sync(0xffffffffu, psum0, 1);
        psum0 += __shfl_xor_sync(0xffffffffu, psum0, 2);
        psum1 += __shfl_xor_sync(0xffffffffu, psum1, 1);
        psum1 += __shfl_xor_sync(0xffffffffu, psum1, 2);
        rsum0 = rsum0 * f0 + psum0;
        rsum1 = rsum1 * f1 + psum1;

#pragma unroll
        for (int nb = 0; nb < 6; nb++) {
            o[nb][0] *= f0; o[nb][1] *= f0;
            o[nb][2] *= f1; o[nb][3] *= f1;
        }
        __syncwarp();

        // ---- PV: O += P x V (bf16 m16n8k16, 4 k-chunks) ----
#pragma unroll
        for (int kb = 0; kb < 4; kb++) {
            uint32_t a0 = Pp[qrow * 36 + kb * 8 + tig];
            uint32_t a1 = Pp[(qrow + 8) * 36 + kb * 8 + tig];
            uint32_t a2 = Pp[qrow * 36 + kb * 8 + tig + 4];
            uint32_t a3 = Pp[(qrow + 8) * 36 + kb * 8 + tig + 4];
#pragma unroll
            for (int nb = 0; nb < 6; nb++) {
                uint32_t b0 = Vp[(nb * 8 + gid) * 36 + kb * 8 + tig];
                uint32_t b1 = Vp[(nb * 8 + gid) * 36 + kb * 8 + tig + 4];
                mma_bf16(o[nb], a0, a1, a2, a3, b0, b1);
            }
        }
    }

    const int mA = m0 + qrow;
    const int mB = mA + 8;
    float* op = g_opart + (split * BB + b) * CC * NN;
#pragma unroll
    for (int nb = 0; nb < 6; nb++) {
        int ch = nb * 8 + 2 * tig;
        op[ch * NN + mA]       = o[nb][0];
        op[(ch + 1) * NN + mA] = o[nb][1];
        op[ch * NN + mB]       = o[nb][2];
        op[(ch + 1) * NN + mB] = o[nb][3];
    }
    if (tig == 0) {
        g_mpart[(split * BB + b) * NN + mA] = rmax0;
        g_mpart[(split * BB + b) * NN + mB] = rmax1;
        g_lpart[(split * BB + b) * NN + mA] = rsum0;
        g_lpart[(split * BB + b) * NN + mB] = rsum1;
    }
}

// ---------------- window attention: 4 windows per 256-thread block --------------
__global__ void __launch_bounds__(256, 4) winattn_kernel() {
    int b  = blockIdx.z;
    int sp = blockIdx.y;
    int wg = threadIdx.x >> 6;
    int w  = blockIdx.x * 4 + wg;
    int t  = threadIdx.x & 63;

    __shared__ float qsm[4][64][17];
    __shared__ float vsm[4][64][17];

    int py, px;
    if (sp == 0)      { int wy = w >> 3, wx = w & 7; py = wy * 8 + (t >> 3); px = wx * 8 + (t & 7); }
    else if (sp == 1) { py = t;  px = w; }
    else              { py = w;  px = t; }
    int pix = py * 64 + px;

    int qbase = (b * 96 + sp * 32) * NN + pix;
#pragma unroll
    for (int c = 0; c < 16; c++) {
        qsm[wg][t][c] = g_x2[qbase + c * NN];
        vsm[wg][t][c] = g_x2[qbase + (16 + c) * NN];
    }
    __syncthreads();

    float qr[16];
#pragma unroll
    for (int c = 0; c < 16; c++) qr[c] = qsm[wg][t][c];

    float lg[64];
    float mx = -1e30f;
    for (int j = 0; j < 64; j++) {
        float d = 0.f;
#pragma unroll
        for (int c = 0; c < 16; c++) d += qr[c] * qsm[wg][j][c];
        lg[j] = d;
        mx = fmaxf(mx, d);
    }
    float s = 0.f;
    for (int j = 0; j < 64; j++) { lg[j] = __expf(lg[j] - mx); s += lg[j]; }
    float inv = 1.f / s;

    float o[16];
#pragma unroll
    for (int c = 0; c < 16; c++) o[c] = 0.f;
    for (int j = 0; j < 64; j++) {
        float p = lg[j] * inv;
#pragma unroll
        for (int c = 0; c < 16; c++) o[c] += p * vsm[wg][j][c];
    }
#pragma unroll
    for (int c = 0; c < 16; c++)
        g_win[(b * CC + sp * 16 + c) * NN + pix] = o[c];
}

// ---------------- final: MMA pout conv + split merge + average -------------------
__global__ void __launch_bounds__(256, 2) final_kernel(
    const float* __restrict__ pw, const float* __restrict__ pb,
    float* __restrict__ out) {
    __shared__ ConvSmem S;
    const int tid = threadIdx.x;
    const int b   = blockIdx.y;
    const int m0  = blockIdx.x * 128;

    if (tid < 48) { S.sc_s[tid] = 1.f; S.bias_s[tid] = pb[tid]; }
    __syncthreads();
    conv_fill(S, g_win + b * CC * NN, m0, pw, tid);
    __syncthreads();

    const int warp = tid >> 5, lane = tid & 31;
    const int gid = lane >> 2, tig = lane & 3;
    const int qrow = warp * 16 + gid;
    float cS[6][4];
    conv_mma(S, cS, qrow, tig, gid);

    const int mA = m0 + qrow;
    const int mB = mA + 8;

    float eA[NSPLIT], eB[NSPLIT];
    {
        float MA = -1e30f, MB = -1e30f;
        float mvA[NSPLIT], mvB[NSPLIT];
#pragma unroll
        for (int s = 0; s < NSPLIT; s++) {
            mvA[s] = g_mpart[(s * BB + b) * NN + mA];
            mvB[s] = g_mpart[(s * BB + b) * NN + mB];
            MA = fmaxf(MA, mvA[s]); MB = fmaxf(MB, mvB[s]);
        }
        float lA = 0.f, lB = 0.f;
#pragma unroll
        for (int s = 0; s < NSPLIT; s++) {
            eA[s] = __expf(mvA[s] - MA);
            eB[s] = __expf(mvB[s] - MB);
            lA += g_lpart[(s * BB + b) * NN + mA] * eA[s];
            lB += g_lpart[(s * BB + b) * NN + mB] * eB[s];
        }
        float ilA = 0.5f / lA, ilB = 0.5f / lB;
#pragma unroll
        for (int s = 0; s < NSPLIT; s++) { eA[s] *= ilA; eB[s] *= ilB; }
    }

#pragma unroll
    for (int nb = 0; nb < 6; nb++) {
        int col = nb * 8 + 2 * tig;
#pragma unroll
        for (int j = 0; j < 2; j++) {
            int ch = col + j;
            float odA = 0.f, odB = 0.f;
#pragma unroll
            for (int s = 0; s < NSPLIT; s++) {
                odA += g_opart[((s * BB + b) * CC + ch) * NN + mA] * eA[s];
                odB += g_opart[((s * BB + b) * CC + ch) * NN + mB] * eB[s];
            }
            out[(b * CC + ch) * NN + mA] = 0.5f * cS[nb][j]     + odA;
            out[(b * CC + ch) * NN + mB] = 0.5f * cS[nb][2 + j] + odB;
        }
    }
}

// ---------------- launch ---------------------------------------------------------
extern "C" void kernel_launch(void* const* d_in, const int* in_sizes, int n_in,
                              void* d_out, int out_size) {
    const float* x        = (const float*)d_in[0];
    const float* Wq       = (const float*)d_in[1];
    const float* bq       = (const float*)d_in[2];
    const float* off_dw_w = (const float*)d_in[3];
    const float* off_dw_b = (const float*)d_in[4];
    const float* off_ln_g = (const float*)d_in[5];
    const float* off_ln_b = (const float*)d_in[6];
    const float* off_pw_w = (const float*)d_in[7];
    const float* Wk       = (const float*)d_in[8];
    const float* bk       = (const float*)d_in[9];
    const float* Wv       = (const float*)d_in[10];
    const float* bv       = (const float*)d_in[11];
    const float* inp_w    = (const float*)d_in[12];
    const float* inp_b    = (const float*)d_in[13];
    const float* bn_g     = (const float*)d_in[14];
    const float* bn_b     = (const float*)d_in[15];
    const float* bn_mean  = (const float*)d_in[16];
    const float* bn_var   = (const float*)d_in[17];
    const float* pout_w   = (const float*)d_in[18];
    const float* pout_b   = (const float*)d_in[19];
    const float* rpe      = (const float*)d_in[20];
    float* out = (float*)d_out;

    cudaFuncSetAttribute(attn_kernel, cudaFuncAttributeMaxDynamicSharedMemorySize,
                         ATTN_SMEM_BYTES);

    stage1_kernel<<<dim3(32, 7), 256>>>(x, Wq, bq, inp_w, inp_b,
                                        bn_g, bn_b, bn_mean, bn_var, rpe);
    deform_kernel<<<dim3(HH, BB), 512>>>(x, off_dw_w, off_dw_b,
                                         off_ln_g, off_ln_b, off_pw_w);
    stage2_kernel<<<dim3(32, 4), 256>>>(Wk, bk, Wv, bv);
    attn_kernel<<<dim3(NN / 128, NSPLIT, BB), 256, ATTN_SMEM_BYTES>>>();
    winattn_kernel<<<dim3(16, 3, BB), 256>>>();
    final_kernel<<<dim3(32, BB), 256>>>(pout_w, pout_b, out);
}

// round 15
// speedup vs baseline: 1.0773x; 1.0773x over previous
#include <cuda_runtime.h>
#include <cuda_bf16.h>
#include <math.h>
#include <stdint.h>

// Problem constants
#define BB 2
#define CC 48
#define HH 64
#define WW 64
#define NN 4096
#define RPE_S 191
#define NSPLIT 4
#define KEYS_PER_SPLIT (NN / NSPLIT)
#define NT (KEYS_PER_SPLIT / 64)

#define RP_ROWS 194
#define RP_STRIDE 196

// ---------------- scratch (device globals; no allocation allowed) -------------
__device__ float  g_q  [BB*CC*NN];       // [c][m] (deform needs this layout)
__device__ float  g_qt [BB*NN*CC];       // [m][c] transposed for attn fills
__device__ float  g_kt [BB*NN*CC];       // [n][c]
__device__ float  g_x2 [BB*96*NN];
__device__ float  g_pos[BB*NN*2];
__device__ float  g_xs [BB*CC*NN];
__device__ float  g_v  [BB*CC*NN];       // [c][n]
__device__ float  g_win[BB*CC*NN];
__device__ float  g_opart[NSPLIT*BB*CC*NN];
__device__ float  g_mpart[NSPLIT*BB*NN];
__device__ float  g_lpart[NSPLIT*BB*NN];
__device__ float4 g_rpe4[RP_ROWS*RP_STRIDE];

// ---------------- MMA helpers -----------------------------------------------------
__device__ __forceinline__ uint32_t f2tf(float f) {
    uint32_t r; asm("cvt.rna.tf32.f32 %0, %1;" : "=r"(r) : "f"(f)); return r;
}
__device__ __forceinline__ void mma_tf32(float* c,
                                         uint32_t a0, uint32_t a1, uint32_t a2, uint32_t a3,
                                         uint32_t b0, uint32_t b1) {
    asm("mma.sync.aligned.m16n8k8.row.col.f32.tf32.tf32.f32 "
        "{%0,%1,%2,%3}, {%4,%5,%6,%7}, {%8,%9}, {%0,%1,%2,%3};"
        : "+f"(c[0]), "+f"(c[1]), "+f"(c[2]), "+f"(c[3])
        : "r"(a0), "r"(a1), "r"(a2), "r"(a3), "r"(b0), "r"(b1));
}
__device__ __forceinline__ void mma_bf16(float* c,
                                         uint32_t a0, uint32_t a1, uint32_t a2, uint32_t a3,
                                         uint32_t b0, uint32_t b1) {
    asm("mma.sync.aligned.m16n8k16.row.col.f32.bf16.bf16.f32 "
        "{%0,%1,%2,%3}, {%4,%5,%6,%7}, {%8,%9}, {%0,%1,%2,%3};"
        : "+f"(c[0]), "+f"(c[1]), "+f"(c[2]), "+f"(c[3])
        : "r"(a0), "r"(a1), "r"(a2), "r"(a3), "r"(b0), "r"(b1));
}
__device__ __forceinline__ uint32_t packbf(float lo, float hi) {
    __nv_bfloat162 h = __floats2bfloat162_rn(lo, hi);
    return *(uint32_t*)&h;
}
__device__ __forceinline__ float2 unpackbf(uint32_t w) {
    __nv_bfloat162 h = *(__nv_bfloat162*)&w;
    return __bfloat1622float2(h);
}

// ---------------- shared 48x48 GEMM tile (128 pixels per block) -------------------
struct ConvSmem {
    float Xs[128 * 52];
    float Ws[48 * 64];
    float bias_s[48];
    float sc_s[48];
};

__device__ __forceinline__ void conv_fill(ConvSmem& S, const float* __restrict__ srcb,
                                          int m0, const float* __restrict__ W, int tid) {
    for (int i = tid; i < CC * 128; i += 256) {
        int c = i >> 7, m = i & 127;
        S.Xs[m * 52 + c] = __uint_as_float(f2tf(srcb[c * NN + m0 + m]));
    }
    for (int i = tid; i < 48 * 64; i += 256) {
        int c = i >> 6, o = i & 63;
        float v = (o < 48) ? W[o * CC + c] * S.sc_s[o] : 0.f;
        S.Ws[c * 64 + (o ^ ((c & 3) << 3))] = __uint_as_float(f2tf(v));
    }
}

__device__ __forceinline__ void conv_mma(const ConvSmem& S, float cS[6][4],
                                         int qrow, int tig, int gid) {
    const uint32_t* Xu = (const uint32_t*)S.Xs;
    const uint32_t* Wu = (const uint32_t*)S.Ws;
#pragma unroll
    for (int nb = 0; nb < 6; nb++) {
        int col = nb * 8 + 2 * tig;
        cS[nb][0] = cS[nb][2] = S.bias_s[col];
        cS[nb][1] = cS[nb][3] = S.bias_s[col + 1];
    }
    const int sw = tig << 3;
#pragma unroll
    for (int kb = 0; kb < 6; kb++) {
        uint32_t a0 = Xu[qrow * 52 + kb * 8 + tig];
        uint32_t a1 = Xu[(qrow + 8) * 52 + kb * 8 + tig];
        uint32_t a2 = Xu[qrow * 52 + kb * 8 + tig + 4];
        uint32_t a3 = Xu[(qrow + 8) * 52 + kb * 8 + tig + 4];
#pragma unroll
        for (int nb = 0; nb < 6; nb++) {
            uint32_t b0 = Wu[(kb * 8 + tig) * 64 + ((nb * 8 + gid) ^ sw)];
            uint32_t b1 = Wu[(kb * 8 + tig + 4) * 64 + ((nb * 8 + gid) ^ sw)];
            mma_tf32(cS[nb], a0, a1, a2, a3, b0, b1);
        }
    }
}

// ---------------- stage1: q + x2(BN) projections + rpe quad-pack -----------------
__global__ void __launch_bounds__(256, 2) stage1_kernel(
    const float* __restrict__ x,
    const float* __restrict__ Wq, const float* __restrict__ bq,
    const float* __restrict__ inp_w, const float* __restrict__ inp_b,
    const float* __restrict__ bng, const float* __restrict__ bnb,
    const float* __restrict__ bnm, const float* __restrict__ bnv,
    const float* __restrict__ rpe) {
    const int tid = threadIdx.x;
    if (blockIdx.y == 6) {
        for (int idx = blockIdx.x * 256 + tid; idx < RP_ROWS * RP_STRIDE; idx += 32 * 256) {
            int r  = idx / RP_STRIDE;
            int xc = idx - r * RP_STRIDE;
            int yy = r - 2, xx = xc - 2;
            float v00 = 0.f, v10 = 0.f, v01 = 0.f, v11 = 0.f;
            bool y0ok = (yy     >= 0 && yy     <= 190);
            bool y1ok = (yy + 1 >= 0 && yy + 1 <= 190);
            if (xx >= 0 && xx <= 190) {
                if (y0ok) v00 = rpe[yy * RPE_S + xx];
                if (y1ok) v10 = rpe[(yy + 1) * RPE_S + xx];
            }
            if (xx + 1 >= 0 && xx + 1 <= 190) {
                if (y0ok) v01 = rpe[yy * RPE_S + xx + 1];
                if (y1ok) v11 = rpe[(yy + 1) * RPE_S + xx + 1];
            }
            g_rpe4[idx] = make_float4(v00, v10, v01, v11);
        }
        return;
    }
    __shared__ ConvSmem S;
    const int job = blockIdx.y >> 1;
    const int b   = blockIdx.y & 1;
    const int m0  = blockIdx.x * 128;

    const float* W;
    const float* bi;
    const float* srcb = x + b * CC * NN;
    float* dstb;
    int bnoff = -1;
    if (job == 0)      { W = Wq;              bi = bq;          dstb = g_q  + b * CC * NN; }
    else if (job == 1) { W = inp_w;           bi = inp_b;       dstb = g_x2 + b * 96 * NN;            bnoff = 0;  }
    else               { W = inp_w + 48 * CC; bi = inp_b + 48;  dstb = g_x2 + (b * 96 + 48) * NN;     bnoff = 48; }

    if (tid < 48) {
        if (bnoff < 0) { S.sc_s[tid] = 1.f; S.bias_s[tid] = bi[tid]; }
        else {
            float sc = rsqrtf(bnv[bnoff + tid] + 1e-5f) * bng[bnoff + tid];
            S.sc_s[tid]   = sc;
            S.bias_s[tid] = (bi[tid] - bnm[bnoff + tid]) * sc + bnb[bnoff + tid];
        }
    }
    __syncthreads();
    conv_fill(S, srcb, m0, W, tid);
    __syncthreads();

    const int warp = tid >> 5, lane = tid & 31;
    const int gid = lane >> 2, tig = lane & 3;
    const int qrow = warp * 16 + gid;
    float cS[6][4];
    conv_mma(S, cS, qrow, tig, gid);

#pragma unroll
    for (int nb = 0; nb < 6; nb++) {
        int col = nb * 8 + 2 * tig;
        dstb[col * NN + m0 + qrow]           = cS[nb][0];
        dstb[(col + 1) * NN + m0 + qrow]     = cS[nb][1];
        dstb[col * NN + m0 + qrow + 8]       = cS[nb][2];
        dstb[(col + 1) * NN + m0 + qrow + 8] = cS[nb][3];
    }
    if (job == 0) {
        float* qt = g_qt + (size_t)b * NN * CC;
#pragma unroll
        for (int nb = 0; nb < 6; nb++) {
            int col = nb * 8 + 2 * tig;
            qt[(m0 + qrow) * CC + col]           = cS[nb][0];
            qt[(m0 + qrow) * CC + col + 1]       = cS[nb][1];
            qt[(m0 + qrow + 8) * CC + col]       = cS[nb][2];
            qt[(m0 + qrow + 8) * CC + col + 1]   = cS[nb][3];
        }
    }
}

// ---------------- stage2: k (transposed), v projections ---------------------------
__global__ void __launch_bounds__(256, 2) stage2_kernel(
    const float* __restrict__ Wk, const float* __restrict__ bk,
    const float* __restrict__ Wv, const float* __restrict__ bv) {
    __shared__ ConvSmem S;
    const int tid = threadIdx.x;
    const int job = blockIdx.y >> 1;
    const int b   = blockIdx.y & 1;
    const int m0  = blockIdx.x * 128;
    const float* W  = job ? Wv : Wk;
    const float* bi = job ? bv : bk;
    const float* srcb = g_xs + b * CC * NN;

    if (tid < 48) { S.sc_s[tid] = 1.f; S.bias_s[tid] = bi[tid]; }
    __syncthreads();
    conv_fill(S, srcb, m0, W, tid);
    __syncthreads();

    const int warp = tid >> 5, lane = tid & 31;
    const int gid = lane >> 2, tig = lane & 3;
    const int qrow = warp * 16 + gid;
    float cS[6][4];
    conv_mma(S, cS, qrow, tig, gid);

    if (job) {
        float* dstb = g_v + b * CC * NN;
#pragma unroll
        for (int nb = 0; nb < 6; nb++) {
            int col = nb * 8 + 2 * tig;
            dstb[col * NN + m0 + qrow]           = cS[nb][0];
            dstb[(col + 1) * NN + m0 + qrow]     = cS[nb][1];
            dstb[col * NN + m0 + qrow + 8]       = cS[nb][2];
            dstb[(col + 1) * NN + m0 + qrow + 8] = cS[nb][3];
        }
    } else {
        float* kt = g_kt + (size_t)b * NN * CC;
#pragma unroll
        for (int nb = 0; nb < 6; nb++) {
            int col = nb * 8 + 2 * tig;
            kt[(m0 + qrow) * CC + col]         = cS[nb][0];
            kt[(m0 + qrow) * CC + col + 1]     = cS[nb][1];
            kt[(m0 + qrow + 8) * CC + col]     = cS[nb][2];
            kt[(m0 + qrow + 8) * CC + col + 1] = cS[nb][3];
        }
    }
}

// ---------------- offset head + position + grid-sample x (512 thr) --------------
__global__ void deform_kernel(const float* __restrict__ x,
                              const float* __restrict__ dww, const float* __restrict__ dwb,
                              const float* __restrict__ lng, const float* __restrict__ lnb,
                              const float* __restrict__ pww) {
    int b = blockIdx.y;
    int y = blockIdx.x;
    int tid = threadIdx.x;
    __shared__ float ts[CC * WW];
    __shared__ float posr[WW * 2];
    __shared__ float redA[8][WW];
    __shared__ float redB[8][WW];

    for (int i = tid; i < CC * WW; i += 512) {
        int c = i >> 6, px = i & 63;
        float acc = dwb[c];
        const float* qc = g_q + (b * CC + c) * NN;
        const float* wc = dww + c * 9;
#pragma unroll
        for (int ky = 0; ky < 3; ky++) {
            int yy = y + ky - 1;
            if (yy < 0 || yy > 63) continue;
#pragma unroll
            for (int kx = 0; kx < 3; kx++) {
                int xx = px + kx - 1;
                if (xx < 0 || xx > 63) continue;
                acc += qc[(yy << 6) + xx] * wc[ky * 3 + kx];
            }
        }
        ts[c * 64 + px] = acc;
    }
    __syncthreads();

    const int sub = tid >> 6;
    const int px  = tid & 63;
    {
        float s = 0.f;
#pragma unroll
        for (int j = 0; j < 6; j++) s += ts[(sub * 6 + j) * 64 + px];
        redA[sub][px] = s;
    }
    __syncthreads();
    float mu = 0.f;
#pragma unroll
    for (int u = 0; u < 8; u++) mu += redA[u][px];
    mu *= (1.f / 48.f);
    {
        float v2 = 0.f;
#pragma unroll
        for (int j = 0; j < 6; j++) {
            float d = ts[(sub * 6 + j) * 64 + px] - mu;
            v2 += d * d;
        }
        redB[sub][px] = v2;
    }
    __syncthreads();
    float var = 0.f;
#pragma unroll
    for (int u = 0; u < 8; u++) var += redB[u][px];
    float rs = rsqrtf(var * (1.f / 48.f) + 1e-5f);
    {
        float a0 = 0.f, a1 = 0.f;
#pragma unroll
        for (int j = 0; j < 6; j++) {
            int c = sub * 6 + j;
            float v = (ts[c * 64 + px] - mu) * rs * lng[c] + lnb[c];
            v = 0.5f * v * (1.f + erff(v * 0.7071067811865475f));
            a0 += pww[c] * v;
            a1 += pww[CC + c] * v;
        }
        redA[sub][px] = a0;
        redB[sub][px] = a1;
    }
    __syncthreads();
    if (tid < WW) {
        float a0 = 0.f, a1 = 0.f;
#pragma unroll
        for (int u = 0; u < 8; u++) { a0 += redA[u][px]; a1 += redB[u][px]; }
        float py  = tanhf(a0) * (2.f / 63.f) + ((0.5f + (float)y ) * (2.f / 63.f) - 1.f);
        float pxx = tanhf(a1) * (2.f / 63.f) + ((0.5f + (float)px) * (2.f / 63.f) - 1.f);
        posr[px * 2 + 0] = py;
        posr[px * 2 + 1] = pxx;
        int n = (y << 6) + px;
        g_pos[(b * NN + n) * 2 + 0] = py;
        g_pos[(b * NN + n) * 2 + 1] = pxx;
    }
    __syncthreads();

    for (int i = tid; i < CC * WW; i += 512) {
        int c = i >> 6, p = i & 63;
        float py  = posr[p * 2 + 0];
        float pxx = posr[p * 2 + 1];
        float gx = (pxx + 1.f) * 0.5f * 63.f;
        float gy = (py  + 1.f) * 0.5f * 63.f;
        const float* img = x + (b * CC + c) * NN;
        float x0f = floorf(gx), y0f = floorf(gy);
        int   x0 = (int)x0f, y0 = (int)y0f;
        float wx = gx - x0f, wy = gy - y0f;
        float acc = 0.f;
#pragma unroll
        for (int dy = 0; dy < 2; dy++) {
            int yc = y0 + dy;
            if (yc < 0 || yc >= HH) continue;
            float wyv = dy ? wy : (1.f - wy);
#pragma unroll
            for (int dx = 0; dx < 2; dx++) {
                int xc = x0 + dx;
                if (xc < 0 || xc >= WW) continue;
                float wxv = dx ? wx : (1.f - wx);
                acc += img[yc * WW + xc] * (wyv * wxv);
            }
        }
        g_xs[(b * CC + c) * NN + (y << 6) + p] = acc;
    }
}

// ---------------- fused flash attention: full bf16 MMA, software pipelined -------
// smem (u32 words): Qp 128x28, Kp[2] 64x28, Vp[2] 48x36, Pp 128x36, Bs[2] 128x33.
#define AOF_QP 0
#define AOF_KP (AOF_QP + 128*28)          // 2 buffers
#define AOF_VP (AOF_KP + 2*64*28)         // 2 buffers
#define AOF_PP (AOF_VP + 2*48*36)
#define AOF_BS (AOF_PP + 128*36)          // 2 buffers, bf16x2 pairs along n
#define ATTN_SMEM_FLOATS (AOF_BS + 2*128*33)
#define ATTN_SMEM_BYTES (ATTN_SMEM_FLOATS * 4)

__global__ void __launch_bounds__(256, 2) attn_kernel() {
    extern __shared__ float sm[];
    uint32_t* Qp  = (uint32_t*)(sm + AOF_QP);
    uint32_t* KpB = (uint32_t*)(sm + AOF_KP);
    uint32_t* VpB = (uint32_t*)(sm + AOF_VP);
    uint32_t* Pp  = (uint32_t*)(sm + AOF_PP);
    uint32_t* BsB = (uint32_t*)(sm + AOF_BS);

    const int yb    = blockIdx.x;
    const int split = blockIdx.y;
    const int b     = blockIdx.z;
    const int tid   = threadIdx.x;
    const int warp  = tid >> 5;
    const int lane  = tid & 31;
    const int gid   = lane >> 2;
    const int tig   = lane & 3;
    const int m0    = yb * 128;
    const int qrow  = warp * 16 + gid;

    const float scale = 0.14433756729740643f;
    const float step  = 95.0f / 63.0f;

    const float* qt = g_qt + (size_t)b * NN * CC;
    const float* kt = g_kt + (size_t)b * NN * CC;
    const float* vb = g_v + b * CC * NN;
    const float* posb = g_pos + b * NN * 2;

    // load Q tile packed: Qp[m][ci] (24 words), scaled bf16
    for (int i = tid; i < 128 * 24; i += 256) {
        int m = i / 24, ci = i - m * 24;
        float2 q2 = *(const float2*)&qt[(m0 + m) * CC + 2 * ci];
        Qp[m * 28 + ci] = packbf(q2.x * scale, q2.y * scale);
    }

    // ---- fill lambda (K, V, bias for tile at n0 into buffer buf) ----
    auto fill_tile = [&](int buf, int n0) {
        uint32_t* Kp = KpB + buf * 64 * 28;
        uint32_t* Vp = VpB + buf * 48 * 36;
        uint32_t* Bs = BsB + buf * 128 * 33;
        // K packed along channels
        for (int i = tid; i < 64 * 24; i += 256) {
            int n = i / 24, ci = i - n * 24;
            float2 k2 = *(const float2*)&kt[(n0 + n) * CC + 2 * ci];
            Kp[n * 28 + ci] = packbf(k2.x, k2.y);
        }
        // V packed along keys
        for (int i = tid; i < 48 * 32; i += 256) {
            int c = i >> 5, pi = i & 31;
            float2 v2 = *(const float2*)&vb[c * NN + n0 + 2 * pi];
            Vp[c * 36 + pi] = packbf(v2.x, v2.y);
        }
        // bias: warp owns 4 key PAIRS; lanes sweep queries; bf16x2 store
#pragma unroll
        for (int kk = 0; kk < 4; kk++) {
            int pi = warp * 4 + kk;          // pair index 0..31
            int n  = 2 * pi;
            float pyA = posb[(n0 + n) * 2 + 0],     pxA = posb[(n0 + n) * 2 + 1];
            float pyB = posb[(n0 + n + 1) * 2 + 0], pxB = posb[(n0 + n + 1) * 2 + 1];
            float kbxA = 47.5f * pxA, kbxB = 47.5f * pxB;
            float fyA[2], fyB[2];
            const float4 *rowA[2], *rowB[2];
#pragma unroll
            for (int r = 0; r < 2; r++) {
                float gyq = 47.5f + (float)(yb * 2 + r) * step;
                float gyA = gyq - 47.5f * pyA;
                float yfA = floorf(gyA);
                int   iyA = (int)yfA;
                fyA[r] = gyA - yfA;
                rowA[r] = g_rpe4 + (min(max(iyA, -2), 191) + 2) * RP_STRIDE;
                float gyB = gyq - 47.5f * pyB;
                float yfB = floorf(gyB);
                int   iyB = (int)yfB;
                fyB[r] = gyB - yfB;
                rowB[r] = g_rpe4 + (min(max(iyB, -2), 191) + 2) * RP_STRIDE;
            }
#pragma unroll
            for (int it = 0; it < 4; it++) {
                int m = it * 32 + lane;
                int r = it >> 1;
                float gxm = 47.5f + (float)(m & 63) * step;
                float biasA, biasB;
                {
                    float gx = gxm - kbxA;
                    float xf = floorf(gx);
                    float fx = gx - xf;
                    int   xi = min(max((int)xf, -2), 192);
                    float4 q4 = rowA[r][xi + 2];
                    float b0 = fmaf(fx, q4.z - q4.x, q4.x);
                    float b1 = fmaf(fx, q4.w - q4.y, q4.y);
                    biasA = fmaf(fyA[r], b1 - b0, b0);
                }
                {
                    float gx = gxm - kbxB;
                    float xf = floorf(gx);
                    float fx = gx - xf;
                    int   xi = min(max((int)xf, -2), 192);
                    float4 q4 = rowB[r][xi + 2];
                    float b0 = fmaf(fx, q4.z - q4.x, q4.x);
                    float b1 = fmaf(fx, q4.w - q4.y, q4.y);
                    biasB = fmaf(fyB[r], b1 - b0, b0);
                }
                Bs[m * 33 + pi] = packbf(biasA, biasB);
            }
        }
    };

    float rmax0 = -1e30f, rmax1 = -1e30f, rsum0 = 0.f, rsum1 = 0.f;
    float o[6][4];
#pragma unroll
    for (int nb = 0; nb < 6; nb++)
#pragma unroll
        for (int j = 0; j < 4; j++) o[nb][j] = 0.f;

    const int nbase = split * KEYS_PER_SPLIT;

    // prologue: fill buffer 0 with tile 0
    fill_tile(0, nbase);
    __syncthreads();

    for (int t = 0; t < NT; t++) {
        const int buf = t & 1;
        // prefetch next tile into the other buffer (overlaps with compute below)
        if (t + 1 < NT) fill_tile(buf ^ 1, nbase + (t + 1) * 64);

        uint32_t* Kp = KpB + buf * 64 * 28;
        uint32_t* Vp = VpB + buf * 48 * 36;
        uint32_t* Bs = BsB + buf * 128 * 33;

        // ---- S = QK^T + bias : C init from Bs (bf16 pairs), bf16 MMA ----
        float cS[8][4];
#pragma unroll
        for (int nb = 0; nb < 8; nb++) {
            float2 bA = unpackbf(Bs[qrow * 33 + nb * 4 + tig]);
            float2 bB = unpackbf(Bs[(qrow + 8) * 33 + nb * 4 + tig]);
            cS[nb][0] = bA.x; cS[nb][1] = bA.y;
            cS[nb][2] = bB.x; cS[nb][3] = bB.y;
        }
#pragma unroll
        for (int kb = 0; kb < 3; kb++) {
            uint32_t a0 = Qp[qrow * 28 + kb * 8 + tig];
            uint32_t a1 = Qp[(qrow + 8) * 28 + kb * 8 + tig];
            uint32_t a2 = Qp[qrow * 28 + kb * 8 + tig + 4];
            uint32_t a3 = Qp[(qrow + 8) * 28 + kb * 8 + tig + 4];
#pragma unroll
            for (int nb = 0; nb < 8; nb++) {
                uint32_t b0 = Kp[(nb * 8 + gid) * 28 + kb * 8 + tig];
                uint32_t b1 = Kp[(nb * 8 + gid) * 28 + kb * 8 + tig + 4];
                mma_bf16(cS[nb], a0, a1, a2, a3, b0, b1);
            }
        }

        // ---- online softmax ----
        float tmax0 = -1e30f, tmax1 = -1e30f;
#pragma unroll
        for (int nb = 0; nb < 8; nb++) {
            tmax0 = fmaxf(tmax0, fmaxf(cS[nb][0], cS[nb][1]));
            tmax1 = fmaxf(tmax1, fmaxf(cS[nb][2], cS[nb][3]));
        }
        tmax0 = fmaxf(tmax0, __shfl_xor_sync(0xffffffffu, tmax0, 1));
        tmax0 = fmaxf(tmax0, __shfl_xor_sync(0xffffffffu, tmax0, 2));
        tmax1 = fmaxf(tmax1, __shfl_xor_sync(0xffffffffu, tmax1, 1));
        tmax1 = fmaxf(tmax1, __shfl_xor_sync(0xffffffffu, tmax1, 2));
        float nmax0 = fmaxf(rmax0, tmax0);
        float nmax1 = fmaxf(rmax1, tmax1);
        float f0 = __expf(rmax0 - nmax0);
        float f1 = __expf(rmax1 - nmax1);
        rmax0 = nmax0; rmax1 = nmax1;

        float psum0 = 0.f, psum1 = 0.f;
#pragma unroll
        for (int nb = 0; nb < 8; nb++) {
            float p0 = __expf(cS[nb][0] - nmax0);
            float p1 = __expf(cS[nb][1] - nmax0);
            float p2 = __expf(cS[nb][2] - nmax1);
            float p3 = __expf(cS[nb][3] - nmax1);
            psum0 += p0 + p1;
            psum1 += p2 + p3;
            Pp[qrow * 36 + nb * 4 + tig]       = packbf(p0, p1);
            Pp[(qrow + 8) * 36 + nb * 4 + tig] = packbf(p2, p3);
        }
        psum0 += __shfl_xor_sync(0xffffffffu, psum0, 1);
        psum0 += __shfl_xor_sync(0xffffffffu, psum0, 2);
        psum1 += __shfl_xor_sync(0xffffffffu, psum1, 1);
        psum1 += __shfl_xor_sync(0xffffffffu, psum1, 2);
        rsum0 = rsum0 * f0 + psum0;
        rsum1 = rsum1 * f1 + psum1;

#pragma unroll
        for (int nb = 0; nb < 6; nb++) {
            o[nb][0] *= f0; o[nb][1] *= f0;
            o[nb][2] *= f1; o[nb][3] *= f1;
        }
        __syncwarp();

        // ---- PV: O += P x V (bf16 m16n8k16, 4 k-chunks) ----
#pragma unroll
        for (int kb = 0; kb < 4; kb++) {
            uint32_t a0 = Pp[qrow * 36 + kb * 8 + tig];
            uint32_t a1 = Pp[(qrow + 8) * 36 + kb * 8 + tig];
            uint32_t a2 = Pp[qrow * 36 + kb * 8 + tig + 4];
            uint32_t a3 = Pp[(qrow + 8) * 36 + kb * 8 + tig + 4];
#pragma unroll
            for (int nb = 0; nb < 6; nb++) {
                uint32_t b0 = Vp[(nb * 8 + gid) * 36 + kb * 8 + tig];
                uint32_t b1 = Vp[(nb * 8 + gid) * 36 + kb * 8 + tig + 4];
                mma_bf16(o[nb], a0, a1, a2, a3, b0, b1);
            }
        }
        __syncthreads();   // next buffer's fills complete; this buffer reusable
    }

    const int mA = m0 + qrow;
    const int mB = mA + 8;
    float* op = g_opart + (split * BB + b) * CC * NN;
#pragma unroll
    for (int nb = 0; nb < 6; nb++) {
        int ch = nb * 8 + 2 * tig;
        op[ch * NN + mA]       = o[nb][0];
        op[(ch + 1) * NN + mA] = o[nb][1];
        op[ch * NN + mB]       = o[nb][2];
        op[(ch + 1) * NN + mB] = o[nb][3];
    }
    if (tig == 0) {
        g_mpart[(split * BB + b) * NN + mA] = rmax0;
        g_mpart[(split * BB + b) * NN + mB] = rmax1;
        g_lpart[(split * BB + b) * NN + mA] = rsum0;
        g_lpart[(split * BB + b) * NN + mB] = rsum1;
    }
}

// ---------------- window attention: 4 windows per 256-thread block --------------
__global__ void __launch_bounds__(256, 4) winattn_kernel() {
    int b  = blockIdx.z;
    int sp = blockIdx.y;
    int wg = threadIdx.x >> 6;
    int w  = blockIdx.x * 4 + wg;
    int t  = threadIdx.x & 63;

    __shared__ float qsm[4][64][17];
    __shared__ float vsm[4][64][17];

    int py, px;
    if (sp == 0)      { int wy = w >> 3, wx = w & 7; py = wy * 8 + (t >> 3); px = wx * 8 + (t & 7); }
    else if (sp == 1) { py = t;  px = w; }
    else              { py = w;  px = t; }
    int pix = py * 64 + px;

    int qbase = (b * 96 + sp * 32) * NN + pix;
#pragma unroll
    for (int c = 0; c < 16; c++) {
        qsm[wg][t][c] = g_x2[qbase + c * NN];
        vsm[wg][t][c] = g_x2[qbase + (16 + c) * NN];
    }
    __syncthreads();

    float qr[16];
#pragma unroll
    for (int c = 0; c < 16; c++) qr[c] = qsm[wg][t][c];

    float lg[64];
    float mx = -1e30f;
    for (int j = 0; j < 64; j++) {
        float d = 0.f;
#pragma unroll
        for (int c = 0; c < 16; c++) d += qr[c] * qsm[wg][j][c];
        lg[j] = d;
        mx = fmaxf(mx, d);
    }
    float s = 0.f;
    for (int j = 0; j < 64; j++) { lg[j] = __expf(lg[j] - mx); s += lg[j]; }
    float inv = 1.f / s;

    float o[16];
#pragma unroll
    for (int c = 0; c < 16; c++) o[c] = 0.f;
    for (int j = 0; j < 64; j++) {
        float p = lg[j] * inv;
#pragma unroll
        for (int c = 0; c < 16; c++) o[c] += p * vsm[wg][j][c];
    }
#pragma unroll
    for (int c = 0; c < 16; c++)
        g_win[(b * CC + sp * 16 + c) * NN + pix] = o[c];
}

// ---------------- final: MMA pout conv + split merge + average -------------------
__global__ void __launch_bounds__(256, 2) final_kernel(
    const float* __restrict__ pw, const float* __restrict__ pb,
    float* __restrict__ out) {
    __shared__ ConvSmem S;
    const int tid = threadIdx.x;
    const int b   = blockIdx.y;
    const int m0  = blockIdx.x * 128;

    if (tid < 48) { S.sc_s[tid] = 1.f; S.bias_s[tid] = pb[tid]; }
    __syncthreads();
    conv_fill(S, g_win + b * CC * NN, m0, pw, tid);
    __syncthreads();

    const int warp = tid >> 5, lane = tid & 31;
    const int gid = lane >> 2, tig = lane & 3;
    const int qrow = warp * 16 + gid;
    float cS[6][4];
    conv_mma(S, cS, qrow, tig, gid);

    const int mA = m0 + qrow;
    const int mB = mA + 8;

    float eA[NSPLIT], eB[NSPLIT];
    {
        float MA = -1e30f, MB = -1e30f;
        float mvA[NSPLIT], mvB[NSPLIT];
#pragma unroll
        for (int s = 0; s < NSPLIT; s++) {
            mvA[s] = g_mpart[(s * BB + b) * NN + mA];
            mvB[s] = g_mpart[(s * BB + b) * NN + mB];
            MA = fmaxf(MA, mvA[s]); MB = fmaxf(MB, mvB[s]);
        }
        float lA = 0.f, lB = 0.f;
#pragma unroll
        for (int s = 0; s < NSPLIT; s++) {
            eA[s] = __expf(mvA[s] - MA);
            eB[s] = __expf(mvB[s] - MB);
            lA += g_lpart[(s * BB + b) * NN + mA] * eA[s];
            lB += g_lpart[(s * BB + b) * NN + mB] * eB[s];
        }
        float ilA = 0.5f / lA, ilB = 0.5f / lB;
#pragma unroll
        for (int s = 0; s < NSPLIT; s++) { eA[s] *= ilA; eB[s] *= ilB; }
    }

#pragma unroll
    for (int nb = 0; nb < 6; nb++) {
        int col = nb * 8 + 2 * tig;
#pragma unroll
        for (int j = 0; j < 2; j++) {
            int ch = col + j;
            float odA = 0.f, odB = 0.f;
#pragma unroll
            for (int s = 0; s < NSPLIT; s++) {
                odA += g_opart[((s * BB + b) * CC + ch) * NN + mA] * eA[s];
                odB += g_opart[((s * BB + b) * CC + ch) * NN + mB] * eB[s];
            }
            out[(b * CC + ch) * NN + mA] = 0.5f * cS[nb][j]     + odA;
            out[(b * CC + ch) * NN + mB] = 0.5f * cS[nb][2 + j] + odB;
        }
    }
}

// ---------------- launch ---------------------------------------------------------
extern "C" void kernel_launch(void* const* d_in, const int* in_sizes, int n_in,
                              void* d_out, int out_size) {
    const float* x        = (const float*)d_in[0];
    const float* Wq       = (const float*)d_in[1];
    const float* bq       = (const float*)d_in[2];
    const float* off_dw_w = (const float*)d_in[3];
    const float* off_dw_b = (const float*)d_in[4];
    const float* off_ln_g = (const float*)d_in[5];
    const float* off_ln_b = (const float*)d_in[6];
    const float* off_pw_w = (const float*)d_in[7];
    const float* Wk       = (const float*)d_in[8];
    const float* bk       = (const float*)d_in[9];
    const float* Wv       = (const float*)d_in[10];
    const float* bv       = (const float*)d_in[11];
    const float* inp_w    = (const float*)d_in[12];
    const float* inp_b    = (const float*)d_in[13];
    const float* bn_g     = (const float*)d_in[14];
    const float* bn_b     = (const float*)d_in[15];
    const float* bn_mean  = (const float*)d_in[16];
    const float* bn_var   = (const float*)d_in[17];
    const float* pout_w   = (const float*)d_in[18];
    const float* pout_b   = (const float*)d_in[19];
    const float* rpe      = (const float*)d_in[20];
    float* out = (float*)d_out;

    cudaFuncSetAttribute(attn_kernel, cudaFuncAttributeMaxDynamicSharedMemorySize,
                         ATTN_SMEM_BYTES);

    stage1_kernel<<<dim3(32, 7), 256>>>(x, Wq, bq, inp_w, inp_b,
                                        bn_g, bn_b, bn_mean, bn_var, rpe);
    deform_kernel<<<dim3(HH, BB), 512>>>(x, off_dw_w, off_dw_b,
                                         off_ln_g, off_ln_b, off_pw_w);
    stage2_kernel<<<dim3(32, 4), 256>>>(Wk, bk, Wv, bv);
    attn_kernel<<<dim3(NN / 128, NSPLIT, BB), 256, ATTN_SMEM_BYTES>>>();
    winattn_kernel<<<dim3(16, 3, BB), 256>>>();
    final_kernel<<<dim3(32, BB), 256>>>(pout_w, pout_b, out);
}

// round 16
// speedup vs baseline: 1.2285x; 1.1404x over previous
#include <cuda_runtime.h>
#include <cuda_bf16.h>
#include <math.h>
#include <stdint.h>

// Problem constants
#define BB 2
#define CC 48
#define HH 64
#define WW 64
#define NN 4096
#define RPE_S 191
#define NSPLIT 4
#define KEYS_PER_SPLIT (NN / NSPLIT)
#define NT (KEYS_PER_SPLIT / 64)

#define RP_ROWS 194
#define RP_STRIDE 196

// ---------------- scratch (device globals; no allocation allowed) -------------
__device__ float    g_q  [BB*CC*NN];     // [c][m] (deform needs this layout)
__device__ uint32_t g_qtp[BB*NN*24];     // [m][ci] bf16x2 pairs, pre-scaled
__device__ uint32_t g_ktp[BB*NN*24];     // [n][ci] bf16x2 pairs
__device__ float    g_x2 [BB*96*NN];
__device__ float    g_pos[BB*NN*2];
__device__ float    g_xs [BB*CC*NN];
__device__ float    g_v  [BB*CC*NN];     // [c][n]
__device__ float    g_win[BB*CC*NN];
__device__ float    g_opart[NSPLIT*BB*CC*NN];
__device__ float    g_mpart[NSPLIT*BB*NN];
__device__ float    g_lpart[NSPLIT*BB*NN];
__device__ float4   g_rpe4[RP_ROWS*RP_STRIDE];

// ---------------- MMA / async helpers ---------------------------------------------
__device__ __forceinline__ uint32_t f2tf(float f) {
    uint32_t r; asm("cvt.rna.tf32.f32 %0, %1;" : "=r"(r) : "f"(f)); return r;
}
__device__ __forceinline__ void mma_tf32(float* c,
                                         uint32_t a0, uint32_t a1, uint32_t a2, uint32_t a3,
                                         uint32_t b0, uint32_t b1) {
    asm("mma.sync.aligned.m16n8k8.row.col.f32.tf32.tf32.f32 "
        "{%0,%1,%2,%3}, {%4,%5,%6,%7}, {%8,%9}, {%0,%1,%2,%3};"
        : "+f"(c[0]), "+f"(c[1]), "+f"(c[2]), "+f"(c[3])
        : "r"(a0), "r"(a1), "r"(a2), "r"(a3), "r"(b0), "r"(b1));
}
__device__ __forceinline__ void mma_bf16(float* c,
                                         uint32_t a0, uint32_t a1, uint32_t a2, uint32_t a3,
                                         uint32_t b0, uint32_t b1) {
    asm("mma.sync.aligned.m16n8k16.row.col.f32.bf16.bf16.f32 "
        "{%0,%1,%2,%3}, {%4,%5,%6,%7}, {%8,%9}, {%0,%1,%2,%3};"
        : "+f"(c[0]), "+f"(c[1]), "+f"(c[2]), "+f"(c[3])
        : "r"(a0), "r"(a1), "r"(a2), "r"(a3), "r"(b0), "r"(b1));
}
__device__ __forceinline__ uint32_t packbf(float lo, float hi) {
    __nv_bfloat162 h = __floats2bfloat162_rn(lo, hi);
    return *(uint32_t*)&h;
}
__device__ __forceinline__ float2 unpackbf(uint32_t w) {
    __nv_bfloat162 h = *(__nv_bfloat162*)&w;
    return __bfloat1622float2(h);
}
__device__ __forceinline__ void cp_async16(uint32_t smem_addr, const void* gptr) {
    asm volatile("cp.async.ca.shared.global [%0], [%1], 16;"
                 :: "r"(smem_addr), "l"(gptr));
}
__device__ __forceinline__ void cp_wait_all() {
    asm volatile("cp.async.wait_all;" ::: "memory");
}

// ---------------- shared 48x48 GEMM tile (128 pixels per block) -------------------
struct ConvSmem {
    float Xs[128 * 52];
    float Ws[48 * 64];
    float bias_s[48];
    float sc_s[48];
};

__device__ __forceinline__ void conv_fill(ConvSmem& S, const float* __restrict__ srcb,
                                          int m0, const float* __restrict__ W, int tid) {
    for (int i = tid; i < CC * 128; i += 256) {
        int c = i >> 7, m = i & 127;
        S.Xs[m * 52 + c] = __uint_as_float(f2tf(srcb[c * NN + m0 + m]));
    }
    for (int i = tid; i < 48 * 64; i += 256) {
        int c = i >> 6, o = i & 63;
        float v = (o < 48) ? W[o * CC + c] * S.sc_s[o] : 0.f;
        S.Ws[c * 64 + (o ^ ((c & 3) << 3))] = __uint_as_float(f2tf(v));
    }
}

__device__ __forceinline__ void conv_mma(const ConvSmem& S, float cS[6][4],
                                         int qrow, int tig, int gid) {
    const uint32_t* Xu = (const uint32_t*)S.Xs;
    const uint32_t* Wu = (const uint32_t*)S.Ws;
#pragma unroll
    for (int nb = 0; nb < 6; nb++) {
        int col = nb * 8 + 2 * tig;
        cS[nb][0] = cS[nb][2] = S.bias_s[col];
        cS[nb][1] = cS[nb][3] = S.bias_s[col + 1];
    }
    const int sw = tig << 3;
#pragma unroll
    for (int kb = 0; kb < 6; kb++) {
        uint32_t a0 = Xu[qrow * 52 + kb * 8 + tig];
        uint32_t a1 = Xu[(qrow + 8) * 52 + kb * 8 + tig];
        uint32_t a2 = Xu[qrow * 52 + kb * 8 + tig + 4];
        uint32_t a3 = Xu[(qrow + 8) * 52 + kb * 8 + tig + 4];
#pragma unroll
        for (int nb = 0; nb < 6; nb++) {
            uint32_t b0 = Wu[(kb * 8 + tig) * 64 + ((nb * 8 + gid) ^ sw)];
            uint32_t b1 = Wu[(kb * 8 + tig + 4) * 64 + ((nb * 8 + gid) ^ sw)];
            mma_tf32(cS[nb], a0, a1, a2, a3, b0, b1);
        }
    }
}

// ---------------- stage1: q + x2(BN) projections + rpe quad-pack -----------------
__global__ void __launch_bounds__(256, 2) stage1_kernel(
    const float* __restrict__ x,
    const float* __restrict__ Wq, const float* __restrict__ bq,
    const float* __restrict__ inp_w, const float* __restrict__ inp_b,
    const float* __restrict__ bng, const float* __restrict__ bnb,
    const float* __restrict__ bnm, const float* __restrict__ bnv,
    const float* __restrict__ rpe) {
    const int tid = threadIdx.x;
    if (blockIdx.y == 6) {
        for (int idx = blockIdx.x * 256 + tid; idx < RP_ROWS * RP_STRIDE; idx += 32 * 256) {
            int r  = idx / RP_STRIDE;
            int xc = idx - r * RP_STRIDE;
            int yy = r - 2, xx = xc - 2;
            float v00 = 0.f, v10 = 0.f, v01 = 0.f, v11 = 0.f;
            bool y0ok = (yy     >= 0 && yy     <= 190);
            bool y1ok = (yy + 1 >= 0 && yy + 1 <= 190);
            if (xx >= 0 && xx <= 190) {
                if (y0ok) v00 = rpe[yy * RPE_S + xx];
                if (y1ok) v10 = rpe[(yy + 1) * RPE_S + xx];
            }
            if (xx + 1 >= 0 && xx + 1 <= 190) {
                if (y0ok) v01 = rpe[yy * RPE_S + xx + 1];
                if (y1ok) v11 = rpe[(yy + 1) * RPE_S + xx + 1];
            }
            g_rpe4[idx] = make_float4(v00, v10, v01, v11);
        }
        return;
    }
    __shared__ ConvSmem S;
    const int job = blockIdx.y >> 1;
    const int b   = blockIdx.y & 1;
    const int m0  = blockIdx.x * 128;
    const float scale = 0.14433756729740643f;

    const float* W;
    const float* bi;
    const float* srcb = x + b * CC * NN;
    float* dstb;
    int bnoff = -1;
    if (job == 0)      { W = Wq;              bi = bq;          dstb = g_q  + b * CC * NN; }
    else if (job == 1) { W = inp_w;           bi = inp_b;       dstb = g_x2 + b * 96 * NN;            bnoff = 0;  }
    else               { W = inp_w + 48 * CC; bi = inp_b + 48;  dstb = g_x2 + (b * 96 + 48) * NN;     bnoff = 48; }

    if (tid < 48) {
        if (bnoff < 0) { S.sc_s[tid] = 1.f; S.bias_s[tid] = bi[tid]; }
        else {
            float sc = rsqrtf(bnv[bnoff + tid] + 1e-5f) * bng[bnoff + tid];
            S.sc_s[tid]   = sc;
            S.bias_s[tid] = (bi[tid] - bnm[bnoff + tid]) * sc + bnb[bnoff + tid];
        }
    }
    __syncthreads();
    conv_fill(S, srcb, m0, W, tid);
    __syncthreads();

    const int warp = tid >> 5, lane = tid & 31;
    const int gid = lane >> 2, tig = lane & 3;
    const int qrow = warp * 16 + gid;
    float cS[6][4];
    conv_mma(S, cS, qrow, tig, gid);

#pragma unroll
    for (int nb = 0; nb < 6; nb++) {
        int col = nb * 8 + 2 * tig;
        dstb[col * NN + m0 + qrow]           = cS[nb][0];
        dstb[(col + 1) * NN + m0 + qrow]     = cS[nb][1];
        dstb[col * NN + m0 + qrow + 8]       = cS[nb][2];
        dstb[(col + 1) * NN + m0 + qrow + 8] = cS[nb][3];
    }
    if (job == 0) {
        uint32_t* qtp = g_qtp + (size_t)b * NN * 24;
#pragma unroll
        for (int nb = 0; nb < 6; nb++) {
            int pi = nb * 4 + tig;
            qtp[(m0 + qrow) * 24 + pi]     = packbf(cS[nb][0] * scale, cS[nb][1] * scale);
            qtp[(m0 + qrow + 8) * 24 + pi] = packbf(cS[nb][2] * scale, cS[nb][3] * scale);
        }
    }
}

// ---------------- stage2: k (packed), v projections -------------------------------
__global__ void __launch_bounds__(256, 2) stage2_kernel(
    const float* __restrict__ Wk, const float* __restrict__ bk,
    const float* __restrict__ Wv, const float* __restrict__ bv) {
    __shared__ ConvSmem S;
    const int tid = threadIdx.x;
    const int job = blockIdx.y >> 1;
    const int b   = blockIdx.y & 1;
    const int m0  = blockIdx.x * 128;
    const float* W  = job ? Wv : Wk;
    const float* bi = job ? bv : bk;
    const float* srcb = g_xs + b * CC * NN;

    if (tid < 48) { S.sc_s[tid] = 1.f; S.bias_s[tid] = bi[tid]; }
    __syncthreads();
    conv_fill(S, srcb, m0, W, tid);
    __syncthreads();

    const int warp = tid >> 5, lane = tid & 31;
    const int gid = lane >> 2, tig = lane & 3;
    const int qrow = warp * 16 + gid;
    float cS[6][4];
    conv_mma(S, cS, qrow, tig, gid);

    if (job) {
        float* dstb = g_v + b * CC * NN;
#pragma unroll
        for (int nb = 0; nb < 6; nb++) {
            int col = nb * 8 + 2 * tig;
            dstb[col * NN + m0 + qrow]           = cS[nb][0];
            dstb[(col + 1) * NN + m0 + qrow]     = cS[nb][1];
            dstb[col * NN + m0 + qrow + 8]       = cS[nb][2];
            dstb[(col + 1) * NN + m0 + qrow + 8] = cS[nb][3];
        }
    } else {
        uint32_t* ktp = g_ktp + (size_t)b * NN * 24;
#pragma unroll
        for (int nb = 0; nb < 6; nb++) {
            int pi = nb * 4 + tig;
            ktp[(m0 + qrow) * 24 + pi]     = packbf(cS[nb][0], cS[nb][1]);
            ktp[(m0 + qrow + 8) * 24 + pi] = packbf(cS[nb][2], cS[nb][3]);
        }
    }
}

// ---------------- offset head + position + grid-sample x (512 thr) --------------
__global__ void deform_kernel(const float* __restrict__ x,
                              const float* __restrict__ dww, const float* __restrict__ dwb,
                              const float* __restrict__ lng, const float* __restrict__ lnb,
                              const float* __restrict__ pww) {
    int b = blockIdx.y;
    int y = blockIdx.x;
    int tid = threadIdx.x;
    __shared__ float ts[CC * WW];
    __shared__ float posr[WW * 2];
    __shared__ float redA[8][WW];
    __shared__ float redB[8][WW];

    for (int i = tid; i < CC * WW; i += 512) {
        int c = i >> 6, px = i & 63;
        float acc = dwb[c];
        const float* qc = g_q + (b * CC + c) * NN;
        const float* wc = dww + c * 9;
#pragma unroll
        for (int ky = 0; ky < 3; ky++) {
            int yy = y + ky - 1;
            if (yy < 0 || yy > 63) continue;
#pragma unroll
            for (int kx = 0; kx < 3; kx++) {
                int xx = px + kx - 1;
                if (xx < 0 || xx > 63) continue;
                acc += qc[(yy << 6) + xx] * wc[ky * 3 + kx];
            }
        }
        ts[c * 64 + px] = acc;
    }
    __syncthreads();

    const int sub = tid >> 6;
    const int px  = tid & 63;
    {
        float s = 0.f;
#pragma unroll
        for (int j = 0; j < 6; j++) s += ts[(sub * 6 + j) * 64 + px];
        redA[sub][px] = s;
    }
    __syncthreads();
    float mu = 0.f;
#pragma unroll
    for (int u = 0; u < 8; u++) mu += redA[u][px];
    mu *= (1.f / 48.f);
    {
        float v2 = 0.f;
#pragma unroll
        for (int j = 0; j < 6; j++) {
            float d = ts[(sub * 6 + j) * 64 + px] - mu;
            v2 += d * d;
        }
        redB[sub][px] = v2;
    }
    __syncthreads();
    float var = 0.f;
#pragma unroll
    for (int u = 0; u < 8; u++) var += redB[u][px];
    float rs = rsqrtf(var * (1.f / 48.f) + 1e-5f);
    {
        float a0 = 0.f, a1 = 0.f;
#pragma unroll
        for (int j = 0; j < 6; j++) {
            int c = sub * 6 + j;
            float v = (ts[c * 64 + px] - mu) * rs * lng[c] + lnb[c];
            v = 0.5f * v * (1.f + erff(v * 0.7071067811865475f));
            a0 += pww[c] * v;
            a1 += pww[CC + c] * v;
        }
        redA[sub][px] = a0;
        redB[sub][px] = a1;
    }
    __syncthreads();
    if (tid < WW) {
        float a0 = 0.f, a1 = 0.f;
#pragma unroll
        for (int u = 0; u < 8; u++) { a0 += redA[u][px]; a1 += redB[u][px]; }
        float py  = tanhf(a0) * (2.f / 63.f) + ((0.5f + (float)y ) * (2.f / 63.f) - 1.f);
        float pxx = tanhf(a1) * (2.f / 63.f) + ((0.5f + (float)px) * (2.f / 63.f) - 1.f);
        posr[px * 2 + 0] = py;
        posr[px * 2 + 1] = pxx;
        int n = (y << 6) + px;
        g_pos[(b * NN + n) * 2 + 0] = py;
        g_pos[(b * NN + n) * 2 + 1] = pxx;
    }
    __syncthreads();

    for (int i = tid; i < CC * WW; i += 512) {
        int c = i >> 6, p = i & 63;
        float py  = posr[p * 2 + 0];
        float pxx = posr[p * 2 + 1];
        float gx = (pxx + 1.f) * 0.5f * 63.f;
        float gy = (py  + 1.f) * 0.5f * 63.f;
        const float* img = x + (b * CC + c) * NN;
        float x0f = floorf(gx), y0f = floorf(gy);
        int   x0 = (int)x0f, y0 = (int)y0f;
        float wx = gx - x0f, wy = gy - y0f;
        float acc = 0.f;
#pragma unroll
        for (int dy = 0; dy < 2; dy++) {
            int yc = y0 + dy;
            if (yc < 0 || yc >= HH) continue;
            float wyv = dy ? wy : (1.f - wy);
#pragma unroll
            for (int dx = 0; dx < 2; dx++) {
                int xc = x0 + dx;
                if (xc < 0 || xc >= WW) continue;
                float wxv = dx ? wx : (1.f - wx);
                acc += img[yc * WW + xc] * (wyv * wxv);
            }
        }
        g_xs[(b * CC + c) * NN + (y << 6) + p] = acc;
    }
}

// ---------------- fused flash attention: bf16 MMA, pipelined, cp.async fills -----
// smem (u32 words): Qp 128x28, Kp[2] 64x28, Vp[2] 48x36, Pp 128x36, Bs[2] 128x33.
#define AOF_QP 0
#define AOF_KP (AOF_QP + 128*28)
#define AOF_VP (AOF_KP + 2*64*28)
#define AOF_PP (AOF_VP + 2*48*36)
#define AOF_BS (AOF_PP + 128*36)
#define ATTN_SMEM_FLOATS (AOF_BS + 2*128*33)
#define ATTN_SMEM_BYTES (ATTN_SMEM_FLOATS * 4)

__global__ void __launch_bounds__(256, 2) attn_kernel() {
    extern __shared__ float sm[];
    uint32_t* Qp  = (uint32_t*)(sm + AOF_QP);
    uint32_t* KpB = (uint32_t*)(sm + AOF_KP);
    uint32_t* VpB = (uint32_t*)(sm + AOF_VP);
    uint32_t* Pp  = (uint32_t*)(sm + AOF_PP);
    uint32_t* BsB = (uint32_t*)(sm + AOF_BS);
    const uint32_t QpA  = (uint32_t)__cvta_generic_to_shared(Qp);
    const uint32_t KpA  = (uint32_t)__cvta_generic_to_shared(KpB);

    const int yb    = blockIdx.x;
    const int split = blockIdx.y;
    const int b     = blockIdx.z;
    const int tid   = threadIdx.x;
    const int warp  = tid >> 5;
    const int lane  = tid & 31;
    const int gid   = lane >> 2;
    const int tig   = lane & 3;
    const int m0    = yb * 128;
    const int qrow  = warp * 16 + gid;

    const float step = 95.0f / 63.0f;

    const uint32_t* qtp = g_qtp + (size_t)b * NN * 24;
    const uint32_t* ktp = g_ktp + (size_t)b * NN * 24;
    const float* vb = g_v + b * CC * NN;
    const float* posb = g_pos + b * NN * 2;

    // Q tile: 128 rows x 6 x 16B via cp.async (pre-scaled bf16 pairs)
    for (int i = tid; i < 128 * 6; i += 256) {
        int m = i / 6, seg = i % 6;
        cp_async16(QpA + (m * 28 + seg * 4) * 4, qtp + (m0 + m) * 24 + seg * 4);
    }

    // ---- fill lambda ----
    auto fill_tile = [&](int buf, int n0) {
        // K: 64 rows x 6 x 16B via cp.async
        uint32_t kbase = KpA + buf * 64 * 28 * 4;
        for (int i = tid; i < 64 * 6; i += 256) {
            int n = i / 6, seg = i % 6;
            cp_async16(kbase + (n * 28 + seg * 4) * 4, ktp + (n0 + n) * 24 + seg * 4);
        }
        // V packed along keys (manual: transpose-pack)
        uint32_t* Vp = VpB + buf * 48 * 36;
        for (int i = tid; i < 48 * 32; i += 256) {
            int c = i >> 5, pi = i & 31;
            float2 v2 = *(const float2*)&vb[c * NN + n0 + 2 * pi];
            Vp[c * 36 + pi] = packbf(v2.x, v2.y);
        }
        // bias: warp owns 4 key pairs; lanes sweep queries; bf16x2 store
        uint32_t* Bs = BsB + buf * 128 * 33;
#pragma unroll
        for (int kk = 0; kk < 4; kk++) {
            int pi = warp * 4 + kk;
            int n  = 2 * pi;
            float pyA = posb[(n0 + n) * 2 + 0],     pxA = posb[(n0 + n) * 2 + 1];
            float pyB = posb[(n0 + n + 1) * 2 + 0], pxB = posb[(n0 + n + 1) * 2 + 1];
            float kbxA = 47.5f * pxA, kbxB = 47.5f * pxB;
            float fyA[2], fyB[2];
            const float4 *rowA[2], *rowB[2];
#pragma unroll
            for (int r = 0; r < 2; r++) {
                float gyq = 47.5f + (float)(yb * 2 + r) * step;
                float gyA = gyq - 47.5f * pyA;
                float yfA = floorf(gyA);
                fyA[r] = gyA - yfA;
                rowA[r] = g_rpe4 + (min(max((int)yfA, -2), 191) + 2) * RP_STRIDE;
                float gyB = gyq - 47.5f * pyB;
                float yfB = floorf(gyB);
                fyB[r] = gyB - yfB;
                rowB[r] = g_rpe4 + (min(max((int)yfB, -2), 191) + 2) * RP_STRIDE;
            }
#pragma unroll
            for (int it = 0; it < 4; it++) {
                int m = it * 32 + lane;
                int r = it >> 1;
                float gxm = 47.5f + (float)(m & 63) * step;
                float biasA, biasB;
                {
                    float gx = gxm - kbxA;
                    float xf = floorf(gx);
                    float fx = gx - xf;
                    int   xi = min(max((int)xf, -2), 192);
                    float4 q4 = rowA[r][xi + 2];
                    float b0 = fmaf(fx, q4.z - q4.x, q4.x);
                    float b1 = fmaf(fx, q4.w - q4.y, q4.y);
                    biasA = fmaf(fyA[r], b1 - b0, b0);
                }
                {
                    float gx = gxm - kbxB;
                    float xf = floorf(gx);
                    float fx = gx - xf;
                    int   xi = min(max((int)xf, -2), 192);
                    float4 q4 = rowB[r][xi + 2];
                    float b0 = fmaf(fx, q4.z - q4.x, q4.x);
                    float b1 = fmaf(fx, q4.w - q4.y, q4.y);
                    biasB = fmaf(fyB[r], b1 - b0, b0);
                }
                Bs[m * 33 + pi] = packbf(biasA, biasB);
            }
        }
    };

    float rmax0 = -1e30f, rmax1 = -1e30f, rsum0 = 0.f, rsum1 = 0.f;
    float o[6][4];
#pragma unroll
    for (int nb = 0; nb < 6; nb++)
#pragma unroll
        for (int j = 0; j < 4; j++) o[nb][j] = 0.f;

    const int nbase = split * KEYS_PER_SPLIT;

    // prologue
    fill_tile(0, nbase);
    cp_wait_all();
    __syncthreads();

    for (int t = 0; t < NT; t++) {
        const int buf = t & 1;
        if (t + 1 < NT) fill_tile(buf ^ 1, nbase + (t + 1) * 64);

        uint32_t* Kp = KpB + buf * 64 * 28;
        uint32_t* Vp = VpB + buf * 48 * 36;
        uint32_t* Bs = BsB + buf * 128 * 33;

        // ---- S = QK^T + bias : C init from Bs, bf16 MMA ----
        float cS[8][4];
#pragma unroll
        for (int nb = 0; nb < 8; nb++) {
            float2 bA = unpackbf(Bs[qrow * 33 + nb * 4 + tig]);
            float2 bB = unpackbf(Bs[(qrow + 8) * 33 + nb * 4 + tig]);
            cS[nb][0] = bA.x; cS[nb][1] = bA.y;
            cS[nb][2] = bB.x; cS[nb][3] = bB.y;
        }
#pragma unroll
        for (int kb = 0; kb < 3; kb++) {
            uint32_t a0 = Qp[qrow * 28 + kb * 8 + tig];
            uint32_t a1 = Qp[(qrow + 8) * 28 + kb * 8 + tig];
            uint32_t a2 = Qp[qrow * 28 + kb * 8 + tig + 4];
            uint32_t a3 = Qp[(qrow + 8) * 28 + kb * 8 + tig + 4];
#pragma unroll
            for (int nb = 0; nb < 8; nb++) {
                uint32_t b0 = Kp[(nb * 8 + gid) * 28 + kb * 8 + tig];
                uint32_t b1 = Kp[(nb * 8 + gid) * 28 + kb * 8 + tig + 4];
                mma_bf16(cS[nb], a0, a1, a2, a3, b0, b1);
            }
        }

        // ---- online softmax ----
        float tmax0 = -1e30f, tmax1 = -1e30f;
#pragma unroll
        for (int nb = 0; nb < 8; nb++) {
            tmax0 = fmaxf(tmax0, fmaxf(cS[nb][0], cS[nb][1]));
            tmax1 = fmaxf(tmax1, fmaxf(cS[nb][2], cS[nb][3]));
        }
        tmax0 = fmaxf(tmax0, __shfl_xor_sync(0xffffffffu, tmax0, 1));
        tmax0 = fmaxf(tmax0, __shfl_xor_sync(0xffffffffu, tmax0, 2));
        tmax1 = fmaxf(tmax1, __shfl_xor_sync(0xffffffffu, tmax1, 1));
        tmax1 = fmaxf(tmax1, __shfl_xor_sync(0xffffffffu, tmax1, 2));
        float nmax0 = fmaxf(rmax0, tmax0);
        float nmax1 = fmaxf(rmax1, tmax1);
        float f0 = __expf(rmax0 - nmax0);
        float f1 = __expf(rmax1 - nmax1);
        rmax0 = nmax0; rmax1 = nmax1;

        float psum0 = 0.f, psum1 = 0.f;
#pragma unroll
        for (int nb = 0; nb < 8; nb++) {
            float p0 = __expf(cS[nb][0] - nmax0);
            float p1 = __expf(cS[nb][1] - nmax0);
            float p2 = __expf(cS[nb][2] - nmax1);
            float p3 = __expf(cS[nb][3] - nmax1);
            psum0 += p0 + p1;
            psum1 += p2 + p3;
            Pp[qrow * 36 + nb * 4 + tig]       = packbf(p0, p1);
            Pp[(qrow + 8) * 36 + nb * 4 + tig] = packbf(p2, p3);
        }
        psum0 += __shfl_xor_sync(0xffffffffu, psum0, 1);
        psum0 += __shfl_xor_sync(0xffffffffu, psum0, 2);
        psum1 += __shfl_xor_sync(0xffffffffu, psum1, 1);
        psum1 += __shfl_xor_sync(0xffffffffu, psum1, 2);
        rsum0 = rsum0 * f0 + psum0;
        rsum1 = rsum1 * f1 + psum1;

#pragma unroll
        for (int nb = 0; nb < 6; nb++) {
            o[nb][0] *= f0; o[nb][1] *= f0;
            o[nb][2] *= f1; o[nb][3] *= f1;
        }
        __syncwarp();

        // ---- PV: O += P x V (bf16 m16n8k16) ----
#pragma unroll
        for (int kb = 0; kb < 4; kb++) {
            uint32_t a0 = Pp[qrow * 36 + kb * 8 + tig];
            uint32_t a1 = Pp[(qrow + 8) * 36 + kb * 8 + tig];
            uint32_t a2 = Pp[qrow * 36 + kb * 8 + tig + 4];
            uint32_t a3 = Pp[(qrow + 8) * 36 + kb * 8 + tig + 4];
#pragma unroll
            for (int nb = 0; nb < 6; nb++) {
                uint32_t b0 = Vp[(nb * 8 + gid) * 36 + kb * 8 + tig];
                uint32_t b1 = Vp[(nb * 8 + gid) * 36 + kb * 8 + tig + 4];
                mma_bf16(o[nb], a0, a1, a2, a3, b0, b1);
            }
        }
        cp_wait_all();     // prefetch K for next tile landed
        __syncthreads();   // all fills visible; buffers swappable
    }

    const int mA = m0 + qrow;
    const int mB = mA + 8;
    float* op = g_opart + (split * BB + b) * CC * NN;
#pragma unroll
    for (int nb = 0; nb < 6; nb++) {
        int ch = nb * 8 + 2 * tig;
        op[ch * NN + mA]       = o[nb][0];
        op[(ch + 1) * NN + mA] = o[nb][1];
        op[ch * NN + mB]       = o[nb][2];
        op[(ch + 1) * NN + mB] = o[nb][3];
    }
    if (tig == 0) {
        g_mpart[(split * BB + b) * NN + mA] = rmax0;
        g_mpart[(split * BB + b) * NN + mB] = rmax1;
        g_lpart[(split * BB + b) * NN + mA] = rsum0;
        g_lpart[(split * BB + b) * NN + mB] = rsum1;
    }
}

// ---------------- window attention: 4 windows per 256-thread block --------------
__global__ void __launch_bounds__(256, 4) winattn_kernel() {
    int b  = blockIdx.z;
    int sp = blockIdx.y;
    int wg = threadIdx.x >> 6;
    int w  = blockIdx.x * 4 + wg;
    int t  = threadIdx.x & 63;

    __shared__ float qsm[4][64][17];
    __shared__ float vsm[4][64][17];

    int py, px;
    if (sp == 0)      { int wy = w >> 3, wx = w & 7; py = wy * 8 + (t >> 3); px = wx * 8 + (t & 7); }
    else if (sp == 1) { py = t;  px = w; }
    else              { py = w;  px = t; }
    int pix = py * 64 + px;

    int qbase = (b * 96 + sp * 32) * NN + pix;
#pragma unroll
    for (int c = 0; c < 16; c++) {
        qsm[wg][t][c] = g_x2[qbase + c * NN];
        vsm[wg][t][c] = g_x2[qbase + (16 + c) * NN];
    }
    __syncthreads();

    float qr[16];
#pragma unroll
    for (int c = 0; c < 16; c++) qr[c] = qsm[wg][t][c];

    float lg[64];
    float mx = -1e30f;
    for (int j = 0; j < 64; j++) {
        float d = 0.f;
#pragma unroll
        for (int c = 0; c < 16; c++) d += qr[c] * qsm[wg][j][c];
        lg[j] = d;
        mx = fmaxf(mx, d);
    }
    float s = 0.f;
    for (int j = 0; j < 64; j++) { lg[j] = __expf(lg[j] - mx); s += lg[j]; }
    float inv = 1.f / s;

    float o[16];
#pragma unroll
    for (int c = 0; c < 16; c++) o[c] = 0.f;
    for (int j = 0; j < 64; j++) {
        float p = lg[j] * inv;
#pragma unroll
        for (int c = 0; c < 16; c++) o[c] += p * vsm[wg][j][c];
    }
#pragma unroll
    for (int c = 0; c < 16; c++)
        g_win[(b * CC + sp * 16 + c) * NN + pix] = o[c];
}

// ---------------- final: MMA pout conv + split merge + average -------------------
__global__ void __launch_bounds__(256, 2) final_kernel(
    const float* __restrict__ pw, const float* __restrict__ pb,
    float* __restrict__ out) {
    __shared__ ConvSmem S;
    const int tid = threadIdx.x;
    const int b   = blockIdx.y;
    const int m0  = blockIdx.x * 128;

    if (tid < 48) { S.sc_s[tid] = 1.f; S.bias_s[tid] = pb[tid]; }
    __syncthreads();
    conv_fill(S, g_win + b * CC * NN, m0, pw, tid);
    __syncthreads();

    const int warp = tid >> 5, lane = tid & 31;
    const int gid = lane >> 2, tig = lane & 3;
    const int qrow = warp * 16 + gid;
    float cS[6][4];
    conv_mma(S, cS, qrow, tig, gid);

    const int mA = m0 + qrow;
    const int mB = mA + 8;

    float eA[NSPLIT], eB[NSPLIT];
    {
        float MA = -1e30f, MB = -1e30f;
        float mvA[NSPLIT], mvB[NSPLIT];
#pragma unroll
        for (int s = 0; s < NSPLIT; s++) {
            mvA[s] = g_mpart[(s * BB + b) * NN + mA];
            mvB[s] = g_mpart[(s * BB + b) * NN + mB];
            MA = fmaxf(MA, mvA[s]); MB = fmaxf(MB, mvB[s]);
        }
        float lA = 0.f, lB = 0.f;
#pragma unroll
        for (int s = 0; s < NSPLIT; s++) {
            eA[s] = __expf(mvA[s] - MA);
            eB[s] = __expf(mvB[s] - MB);
            lA += g_lpart[(s * BB + b) * NN + mA] * eA[s];
            lB += g_lpart[(s * BB + b) * NN + mB] * eB[s];
        }
        float ilA = 0.5f / lA, ilB = 0.5f / lB;
#pragma unroll
        for (int s = 0; s < NSPLIT; s++) { eA[s] *= ilA; eB[s] *= ilB; }
    }

#pragma unroll
    for (int nb = 0; nb < 6; nb++) {
        int col = nb * 8 + 2 * tig;
#pragma unroll
        for (int j = 0; j < 2; j++) {
            int ch = col + j;
            float odA = 0.f, odB = 0.f;
#pragma unroll
            for (int s = 0; s < NSPLIT; s++) {
                odA += g_opart[((s * BB + b) * CC + ch) * NN + mA] * eA[s];
                odB += g_opart[((s * BB + b) * CC + ch) * NN + mB] * eB[s];
            }
            out[(b * CC + ch) * NN + mA] = 0.5f * cS[nb][j]     + odA;
            out[(b * CC + ch) * NN + mB] = 0.5f * cS[nb][2 + j] + odB;
        }
    }
}

// ---------------- launch ---------------------------------------------------------
extern "C" void kernel_launch(void* const* d_in, const int* in_sizes, int n_in,
                              void* d_out, int out_size) {
    const float* x        = (const float*)d_in[0];
    const float* Wq       = (const float*)d_in[1];
    const float* bq       = (const float*)d_in[2];
    const float* off_dw_w = (const float*)d_in[3];
    const float* off_dw_b = (const float*)d_in[4];
    const float* off_ln_g = (const float*)d_in[5];
    const float* off_ln_b = (const float*)d_in[6];
    const float* off_pw_w = (const float*)d_in[7];
    const float* Wk       = (const float*)d_in[8];
    const float* bk       = (const float*)d_in[9];
    const float* Wv       = (const float*)d_in[10];
    const float* bv       = (const float*)d_in[11];
    const float* inp_w    = (const float*)d_in[12];
    const float* inp_b    = (const float*)d_in[13];
    const float* bn_g     = (const float*)d_in[14];
    const float* bn_b     = (const float*)d_in[15];
    const float* bn_mean  = (const float*)d_in[16];
    const float* bn_var   = (const float*)d_in[17];
    const float* pout_w   = (const float*)d_in[18];
    const float* pout_b   = (const float*)d_in[19];
    const float* rpe      = (const float*)d_in[20];
    float* out = (float*)d_out;

    cudaFuncSetAttribute(attn_kernel, cudaFuncAttributeMaxDynamicSharedMemorySize,
                         ATTN_SMEM_BYTES);

    stage1_kernel<<<dim3(32, 7), 256>>>(x, Wq, bq, inp_w, inp_b,
                                        bn_g, bn_b, bn_mean, bn_var, rpe);
    deform_kernel<<<dim3(HH, BB), 512>>>(x, off_dw_w, off_dw_b,
                                         off_ln_g, off_ln_b, off_pw_w);
    stage2_kernel<<<dim3(32, 4), 256>>>(Wk, bk, Wv, bv);
    attn_kernel<<<dim3(NN / 128, NSPLIT, BB), 256, ATTN_SMEM_BYTES>>>();
    winattn_kernel<<<dim3(16, 3, BB), 256>>>();
    final_kernel<<<dim3(32, BB), 256>>>(pout_w, pout_b, out);
}

// round 17
// speedup vs baseline: 1.3707x; 1.1157x over previous
#include <cuda_runtime.h>
#include <cuda_bf16.h>
#include <math.h>
#include <stdint.h>

// Problem constants
#define BB 2
#define CC 48
#define HH 64
#define WW 64
#define NN 4096
#define RPE_S 191
#define NSPLIT 4
#define KEYS_PER_SPLIT (NN / NSPLIT)
#define NT (KEYS_PER_SPLIT / 64)

#define RP_ROWS 194
#define RP_STRIDE 196

// ---------------- scratch (device globals; no allocation allowed) -------------
__device__ float          g_q  [BB*CC*NN];   // [c][m] (deform needs this layout)
__device__ uint32_t       g_qtp[BB*NN*24];   // [m][ci] bf16x2 pairs, pre-scaled
__device__ uint32_t       g_ktp[BB*NN*24];   // [n][ci] bf16x2 pairs
__device__ __nv_bfloat16  g_vh [BB*CC*NN];   // [c][n] bf16
__device__ float          g_x2 [BB*96*NN];
__device__ float          g_pos[BB*NN*2];
__device__ float          g_xs [BB*CC*NN];
__device__ float          g_win[BB*CC*NN];
__device__ float          g_opart[NSPLIT*BB*CC*NN];
__device__ float          g_mpart[NSPLIT*BB*NN];
__device__ float          g_lpart[NSPLIT*BB*NN];
// bf16 quad rpe table: (v00, v10, v01, v11) packed into uint2
__device__ uint2          g_rpe4h[RP_ROWS*RP_STRIDE];

// ---------------- MMA / async helpers ---------------------------------------------
__device__ __forceinline__ uint32_t f2tf(float f) {
    uint32_t r; asm("cvt.rna.tf32.f32 %0, %1;" : "=r"(r) : "f"(f)); return r;
}
__device__ __forceinline__ void mma_tf32(float* c,
                                         uint32_t a0, uint32_t a1, uint32_t a2, uint32_t a3,
                                         uint32_t b0, uint32_t b1) {
    asm("mma.sync.aligned.m16n8k8.row.col.f32.tf32.tf32.f32 "
        "{%0,%1,%2,%3}, {%4,%5,%6,%7}, {%8,%9}, {%0,%1,%2,%3};"
        : "+f"(c[0]), "+f"(c[1]), "+f"(c[2]), "+f"(c[3])
        : "r"(a0), "r"(a1), "r"(a2), "r"(a3), "r"(b0), "r"(b1));
}
__device__ __forceinline__ void mma_bf16(float* c,
                                         uint32_t a0, uint32_t a1, uint32_t a2, uint32_t a3,
                                         uint32_t b0, uint32_t b1) {
    asm("mma.sync.aligned.m16n8k16.row.col.f32.bf16.bf16.f32 "
        "{%0,%1,%2,%3}, {%4,%5,%6,%7}, {%8,%9}, {%0,%1,%2,%3};"
        : "+f"(c[0]), "+f"(c[1]), "+f"(c[2]), "+f"(c[3])
        : "r"(a0), "r"(a1), "r"(a2), "r"(a3), "r"(b0), "r"(b1));
}
__device__ __forceinline__ uint32_t packbf(float lo, float hi) {
    __nv_bfloat162 h = __floats2bfloat162_rn(lo, hi);
    return *(uint32_t*)&h;
}
__device__ __forceinline__ float2 unpackbf(uint32_t w) {
    __nv_bfloat162 h = *(__nv_bfloat162*)&w;
    return __bfloat1622float2(h);
}
__device__ __forceinline__ void cp_async16(uint32_t smem_addr, const void* gptr) {
    asm volatile("cp.async.ca.shared.global [%0], [%1], 16;"
                 :: "r"(smem_addr), "l"(gptr));
}
__device__ __forceinline__ void cp_wait_all() {
    asm volatile("cp.async.wait_all;" ::: "memory");
}

// ---------------- shared 48x48 GEMM tile (128 pixels per block) -------------------
struct ConvSmem {
    float Xs[128 * 52];
    float Ws[48 * 64];
    float bias_s[48];
    float sc_s[48];
};

__device__ __forceinline__ void conv_fill(ConvSmem& S, const float* __restrict__ srcb,
                                          int m0, const float* __restrict__ W, int tid) {
    for (int i = tid; i < CC * 128; i += 256) {
        int c = i >> 7, m = i & 127;
        S.Xs[m * 52 + c] = __uint_as_float(f2tf(srcb[c * NN + m0 + m]));
    }
    for (int i = tid; i < 48 * 64; i += 256) {
        int c = i >> 6, o = i & 63;
        float v = (o < 48) ? W[o * CC + c] * S.sc_s[o] : 0.f;
        S.Ws[c * 64 + (o ^ ((c & 3) << 3))] = __uint_as_float(f2tf(v));
    }
}

__device__ __forceinline__ void conv_mma(const ConvSmem& S, float cS[6][4],
                                         int qrow, int tig, int gid) {
    const uint32_t* Xu = (const uint32_t*)S.Xs;
    const uint32_t* Wu = (const uint32_t*)S.Ws;
#pragma unroll
    for (int nb = 0; nb < 6; nb++) {
        int col = nb * 8 + 2 * tig;
        cS[nb][0] = cS[nb][2] = S.bias_s[col];
        cS[nb][1] = cS[nb][3] = S.bias_s[col + 1];
    }
    const int sw = tig << 3;
#pragma unroll
    for (int kb = 0; kb < 6; kb++) {
        uint32_t a0 = Xu[qrow * 52 + kb * 8 + tig];
        uint32_t a1 = Xu[(qrow + 8) * 52 + kb * 8 + tig];
        uint32_t a2 = Xu[qrow * 52 + kb * 8 + tig + 4];
        uint32_t a3 = Xu[(qrow + 8) * 52 + kb * 8 + tig + 4];
#pragma unroll
        for (int nb = 0; nb < 6; nb++) {
            uint32_t b0 = Wu[(kb * 8 + tig) * 64 + ((nb * 8 + gid) ^ sw)];
            uint32_t b1 = Wu[(kb * 8 + tig + 4) * 64 + ((nb * 8 + gid) ^ sw)];
            mma_tf32(cS[nb], a0, a1, a2, a3, b0, b1);
        }
    }
}

// ---------------- stage1: q + x2(BN) projections + rpe bf16 quad-pack ------------
__global__ void __launch_bounds__(256, 2) stage1_kernel(
    const float* __restrict__ x,
    const float* __restrict__ Wq, const float* __restrict__ bq,
    const float* __restrict__ inp_w, const float* __restrict__ inp_b,
    const float* __restrict__ bng, const float* __restrict__ bnb,
    const float* __restrict__ bnm, const float* __restrict__ bnv,
    const float* __restrict__ rpe) {
    const int tid = threadIdx.x;
    if (blockIdx.y == 6) {
        for (int idx = blockIdx.x * 256 + tid; idx < RP_ROWS * RP_STRIDE; idx += 32 * 256) {
            int r  = idx / RP_STRIDE;
            int xc = idx - r * RP_STRIDE;
            int yy = r - 2, xx = xc - 2;
            float v00 = 0.f, v10 = 0.f, v01 = 0.f, v11 = 0.f;
            bool y0ok = (yy     >= 0 && yy     <= 190);
            bool y1ok = (yy + 1 >= 0 && yy + 1 <= 190);
            if (xx >= 0 && xx <= 190) {
                if (y0ok) v00 = rpe[yy * RPE_S + xx];
                if (y1ok) v10 = rpe[(yy + 1) * RPE_S + xx];
            }
            if (xx + 1 >= 0 && xx + 1 <= 190) {
                if (y0ok) v01 = rpe[yy * RPE_S + xx + 1];
                if (y1ok) v11 = rpe[(yy + 1) * RPE_S + xx + 1];
            }
            g_rpe4h[idx] = make_uint2(packbf(v00, v10), packbf(v01, v11));
        }
        return;
    }
    __shared__ ConvSmem S;
    const int job = blockIdx.y >> 1;
    const int b   = blockIdx.y & 1;
    const int m0  = blockIdx.x * 128;
    const float scale = 0.14433756729740643f;

    const float* W;
    const float* bi;
    const float* srcb = x + b * CC * NN;
    float* dstb;
    int bnoff = -1;
    if (job == 0)      { W = Wq;              bi = bq;          dstb = g_q  + b * CC * NN; }
    else if (job == 1) { W = inp_w;           bi = inp_b;       dstb = g_x2 + b * 96 * NN;            bnoff = 0;  }
    else               { W = inp_w + 48 * CC; bi = inp_b + 48;  dstb = g_x2 + (b * 96 + 48) * NN;     bnoff = 48; }

    if (tid < 48) {
        if (bnoff < 0) { S.sc_s[tid] = 1.f; S.bias_s[tid] = bi[tid]; }
        else {
            float sc = rsqrtf(bnv[bnoff + tid] + 1e-5f) * bng[bnoff + tid];
            S.sc_s[tid]   = sc;
            S.bias_s[tid] = (bi[tid] - bnm[bnoff + tid]) * sc + bnb[bnoff + tid];
        }
    }
    __syncthreads();
    conv_fill(S, srcb, m0, W, tid);
    __syncthreads();

    const int warp = tid >> 5, lane = tid & 31;
    const int gid = lane >> 2, tig = lane & 3;
    const int qrow = warp * 16 + gid;
    float cS[6][4];
    conv_mma(S, cS, qrow, tig, gid);

#pragma unroll
    for (int nb = 0; nb < 6; nb++) {
        int col = nb * 8 + 2 * tig;
        dstb[col * NN + m0 + qrow]           = cS[nb][0];
        dstb[(col + 1) * NN + m0 + qrow]     = cS[nb][1];
        dstb[col * NN + m0 + qrow + 8]       = cS[nb][2];
        dstb[(col + 1) * NN + m0 + qrow + 8] = cS[nb][3];
    }
    if (job == 0) {
        uint32_t* qtp = g_qtp + (size_t)b * NN * 24;
#pragma unroll
        for (int nb = 0; nb < 6; nb++) {
            int pi = nb * 4 + tig;
            qtp[(m0 + qrow) * 24 + pi]     = packbf(cS[nb][0] * scale, cS[nb][1] * scale);
            qtp[(m0 + qrow + 8) * 24 + pi] = packbf(cS[nb][2] * scale, cS[nb][3] * scale);
        }
    }
}

// ---------------- stage2: k (packed), v (bf16) projections ------------------------
__global__ void __launch_bounds__(256, 2) stage2_kernel(
    const float* __restrict__ Wk, const float* __restrict__ bk,
    const float* __restrict__ Wv, const float* __restrict__ bv) {
    __shared__ ConvSmem S;
    const int tid = threadIdx.x;
    const int job = blockIdx.y >> 1;
    const int b   = blockIdx.y & 1;
    const int m0  = blockIdx.x * 128;
    const float* W  = job ? Wv : Wk;
    const float* bi = job ? bv : bk;
    const float* srcb = g_xs + b * CC * NN;

    if (tid < 48) { S.sc_s[tid] = 1.f; S.bias_s[tid] = bi[tid]; }
    __syncthreads();
    conv_fill(S, srcb, m0, W, tid);
    __syncthreads();

    const int warp = tid >> 5, lane = tid & 31;
    const int gid = lane >> 2, tig = lane & 3;
    const int qrow = warp * 16 + gid;
    float cS[6][4];
    conv_mma(S, cS, qrow, tig, gid);

    if (job) {
        __nv_bfloat16* dsth = g_vh + (size_t)b * CC * NN;
#pragma unroll
        for (int nb = 0; nb < 6; nb++) {
            int col = nb * 8 + 2 * tig;
            dsth[col * NN + m0 + qrow]           = __float2bfloat16(cS[nb][0]);
            dsth[(col + 1) * NN + m0 + qrow]     = __float2bfloat16(cS[nb][1]);
            dsth[col * NN + m0 + qrow + 8]       = __float2bfloat16(cS[nb][2]);
            dsth[(col + 1) * NN + m0 + qrow + 8] = __float2bfloat16(cS[nb][3]);
        }
    } else {
        uint32_t* ktp = g_ktp + (size_t)b * NN * 24;
#pragma unroll
        for (int nb = 0; nb < 6; nb++) {
            int pi = nb * 4 + tig;
            ktp[(m0 + qrow) * 24 + pi]     = packbf(cS[nb][0], cS[nb][1]);
            ktp[(m0 + qrow + 8) * 24 + pi] = packbf(cS[nb][2], cS[nb][3]);
        }
    }
}

// ---------------- offset head + position + grid-sample x (512 thr) --------------
__global__ void deform_kernel(const float* __restrict__ x,
                              const float* __restrict__ dww, const float* __restrict__ dwb,
                              const float* __restrict__ lng, const float* __restrict__ lnb,
                              const float* __restrict__ pww) {
    int b = blockIdx.y;
    int y = blockIdx.x;
    int tid = threadIdx.x;
    __shared__ float ts[CC * WW];
    __shared__ float posr[WW * 2];
    __shared__ float redA[8][WW];
    __shared__ float redB[8][WW];

    for (int i = tid; i < CC * WW; i += 512) {
        int c = i >> 6, px = i & 63;
        float acc = dwb[c];
        const float* qc = g_q + (b * CC + c) * NN;
        const float* wc = dww + c * 9;
#pragma unroll
        for (int ky = 0; ky < 3; ky++) {
            int yy = y + ky - 1;
            if (yy < 0 || yy > 63) continue;
#pragma unroll
            for (int kx = 0; kx < 3; kx++) {
                int xx = px + kx - 1;
                if (xx < 0 || xx > 63) continue;
                acc += qc[(yy << 6) + xx] * wc[ky * 3 + kx];
            }
        }
        ts[c * 64 + px] = acc;
    }
    __syncthreads();

    const int sub = tid >> 6;
    const int px  = tid & 63;
    {
        float s = 0.f;
#pragma unroll
        for (int j = 0; j < 6; j++) s += ts[(sub * 6 + j) * 64 + px];
        redA[sub][px] = s;
    }
    __syncthreads();
    float mu = 0.f;
#pragma unroll
    for (int u = 0; u < 8; u++) mu += redA[u][px];
    mu *= (1.f / 48.f);
    {
        float v2 = 0.f;
#pragma unroll
        for (int j = 0; j < 6; j++) {
            float d = ts[(sub * 6 + j) * 64 + px] - mu;
            v2 += d * d;
        }
        redB[sub][px] = v2;
    }
    __syncthreads();
    float var = 0.f;
#pragma unroll
    for (int u = 0; u < 8; u++) var += redB[u][px];
    float rs = rsqrtf(var * (1.f / 48.f) + 1e-5f);
    {
        float a0 = 0.f, a1 = 0.f;
#pragma unroll
        for (int j = 0; j < 6; j++) {
            int c = sub * 6 + j;
            float v = (ts[c * 64 + px] - mu) * rs * lng[c] + lnb[c];
            v = 0.5f * v * (1.f + erff(v * 0.7071067811865475f));
            a0 += pww[c] * v;
            a1 += pww[CC + c] * v;
        }
        redA[sub][px] = a0;
        redB[sub][px] = a1;
    }
    __syncthreads();
    if (tid < WW) {
        float a0 = 0.f, a1 = 0.f;
#pragma unroll
        for (int u = 0; u < 8; u++) { a0 += redA[u][px]; a1 += redB[u][px]; }
        float py  = tanhf(a0) * (2.f / 63.f) + ((0.5f + (float)y ) * (2.f / 63.f) - 1.f);
        float pxx = tanhf(a1) * (2.f / 63.f) + ((0.5f + (float)px) * (2.f / 63.f) - 1.f);
        posr[px * 2 + 0] = py;
        posr[px * 2 + 1] = pxx;
        int n = (y << 6) + px;
        g_pos[(b * NN + n) * 2 + 0] = py;
        g_pos[(b * NN + n) * 2 + 1] = pxx;
    }
    __syncthreads();

    for (int i = tid; i < CC * WW; i += 512) {
        int c = i >> 6, p = i & 63;
        float py  = posr[p * 2 + 0];
        float pxx = posr[p * 2 + 1];
        float gx = (pxx + 1.f) * 0.5f * 63.f;
        float gy = (py  + 1.f) * 0.5f * 63.f;
        const float* img = x + (b * CC + c) * NN;
        float x0f = floorf(gx), y0f = floorf(gy);
        int   x0 = (int)x0f, y0 = (int)y0f;
        float wx = gx - x0f, wy = gy - y0f;
        float acc = 0.f;
#pragma unroll
        for (int dy = 0; dy < 2; dy++) {
            int yc = y0 + dy;
            if (yc < 0 || yc >= HH) continue;
            float wyv = dy ? wy : (1.f - wy);
#pragma unroll
            for (int dx = 0; dx < 2; dx++) {
                int xc = x0 + dx;
                if (xc < 0 || xc >= WW) continue;
                float wxv = dx ? wx : (1.f - wx);
                acc += img[yc * WW + xc] * (wyv * wxv);
            }
        }
        g_xs[(b * CC + c) * NN + (y << 6) + p] = acc;
    }
}

// ---------------- fused flash attention: bf16 MMA, pipelined, async fills --------
// smem (u32 words): Qp 128x28, Kp[2] 64x28, Vp[2] 48x36, Pp 128x36, Bs[2] 128x33.
#define AOF_QP 0
#define AOF_KP (AOF_QP + 128*28)
#define AOF_VP (AOF_KP + 2*64*28)
#define AOF_PP (AOF_VP + 2*48*36)
#define AOF_BS (AOF_PP + 128*36)
#define ATTN_SMEM_FLOATS (AOF_BS + 2*128*33)
#define ATTN_SMEM_BYTES (ATTN_SMEM_FLOATS * 4)

__global__ void __launch_bounds__(256, 2) attn_kernel() {
    extern __shared__ float sm[];
    uint32_t* Qp  = (uint32_t*)(sm + AOF_QP);
    uint32_t* KpB = (uint32_t*)(sm + AOF_KP);
    uint32_t* VpB = (uint32_t*)(sm + AOF_VP);
    uint32_t* Pp  = (uint32_t*)(sm + AOF_PP);
    uint32_t* BsB = (uint32_t*)(sm + AOF_BS);
    const uint32_t QpA = (uint32_t)__cvta_generic_to_shared(Qp);
    const uint32_t KpA = (uint32_t)__cvta_generic_to_shared(KpB);
    const uint32_t VpA = (uint32_t)__cvta_generic_to_shared(VpB);

    const int yb    = blockIdx.x;
    const int split = blockIdx.y;
    const int b     = blockIdx.z;
    const int tid   = threadIdx.x;
    const int warp  = tid >> 5;
    const int lane  = tid & 31;
    const int gid   = lane >> 2;
    const int tig   = lane & 3;
    const int m0    = yb * 128;
    const int qrow  = warp * 16 + gid;

    const float step = 95.0f / 63.0f;

    const uint32_t* qtp = g_qtp + (size_t)b * NN * 24;
    const uint32_t* ktp = g_ktp + (size_t)b * NN * 24;
    const __nv_bfloat16* vh = g_vh + (size_t)b * CC * NN;
    const float* posb = g_pos + b * NN * 2;

    // Q tile: 128 rows x 6 x 16B via cp.async (pre-scaled bf16 pairs)
    for (int i = tid; i < 128 * 6; i += 256) {
        int m = i / 6, seg = i % 6;
        cp_async16(QpA + (m * 28 + seg * 4) * 4, qtp + (m0 + m) * 24 + seg * 4);
    }

    // ---- fill lambda ----
    auto fill_tile = [&](int buf, int n0) {
        // K: 64 rows x 6 x 16B via cp.async
        uint32_t kbase = KpA + buf * 64 * 28 * 4;
        for (int i = tid; i < 64 * 6; i += 256) {
            int n = i / 6, seg = i % 6;
            cp_async16(kbase + (n * 28 + seg * 4) * 4, ktp + (n0 + n) * 24 + seg * 4);
        }
        // V: 48 rows x 8 x 16B (8 bf16 keys each) via cp.async
        uint32_t vbase = VpA + buf * 48 * 36 * 4;
        for (int i = tid; i < 48 * 8; i += 256) {
            int c = i >> 3, seg = i & 7;
            cp_async16(vbase + (c * 36 + seg * 4) * 4, vh + c * NN + n0 + seg * 8);
        }
        // bias: warp owns 4 key pairs; lanes sweep queries; bf16x2 store
        uint32_t* Bs = BsB + buf * 128 * 33;
#pragma unroll
        for (int kk = 0; kk < 4; kk++) {
            int pi = warp * 4 + kk;
            int n  = 2 * pi;
            float pyA = posb[(n0 + n) * 2 + 0],     pxA = posb[(n0 + n) * 2 + 1];
            float pyB = posb[(n0 + n + 1) * 2 + 0], pxB = posb[(n0 + n + 1) * 2 + 1];
            float kbxA = 47.5f * pxA, kbxB = 47.5f * pxB;
            float fyA[2], fyB[2];
            const uint2 *rowA[2], *rowB[2];
#pragma unroll
            for (int r = 0; r < 2; r++) {
                float gyq = 47.5f + (float)(yb * 2 + r) * step;
                float gyA = gyq - 47.5f * pyA;
                float yfA = floorf(gyA);
                fyA[r] = gyA - yfA;
                rowA[r] = g_rpe4h + (min(max((int)yfA, -2), 191) + 2) * RP_STRIDE;
                float gyB = gyq - 47.5f * pyB;
                float yfB = floorf(gyB);
                fyB[r] = gyB - yfB;
                rowB[r] = g_rpe4h + (min(max((int)yfB, -2), 191) + 2) * RP_STRIDE;
            }
#pragma unroll
            for (int it = 0; it < 4; it++) {
                int m = it * 32 + lane;
                int r = it >> 1;
                float gxm = 47.5f + (float)(m & 63) * step;
                float biasA, biasB;
                {
                    float gx = gxm - kbxA;
                    float xf = floorf(gx);
                    float fx = gx - xf;
                    int   xi = min(max((int)xf, -2), 192);
                    uint2 q2 = rowA[r][xi + 2];
                    float2 lo = unpackbf(q2.x);    // (v00, v10)
                    float2 hi = unpackbf(q2.y);    // (v01, v11)
                    float b0 = fmaf(fx, hi.x - lo.x, lo.x);
                    float b1 = fmaf(fx, hi.y - lo.y, lo.y);
                    biasA = fmaf(fyA[r], b1 - b0, b0);
                }
                {
                    float gx = gxm - kbxB;
                    float xf = floorf(gx);
                    float fx = gx - xf;
                    int   xi = min(max((int)xf, -2), 192);
                    uint2 q2 = rowB[r][xi + 2];
                    float2 lo = unpackbf(q2.x);
                    float2 hi = unpackbf(q2.y);
                    float b0 = fmaf(fx, hi.x - lo.x, lo.x);
                    float b1 = fmaf(fx, hi.y - lo.y, lo.y);
                    biasB = fmaf(fyB[r], b1 - b0, b0);
                }
                Bs[m * 33 + pi] = packbf(biasA, biasB);
            }
        }
    };

    float rmax0 = -1e30f, rmax1 = -1e30f, rsum0 = 0.f, rsum1 = 0.f;
    float o[6][4];
#pragma unroll
    for (int nb = 0; nb < 6; nb++)
#pragma unroll
        for (int j = 0; j < 4; j++) o[nb][j] = 0.f;

    const int nbase = split * KEYS_PER_SPLIT;

    // prologue
    fill_tile(0, nbase);
    cp_wait_all();
    __syncthreads();

    for (int t = 0; t < NT; t++) {
        const int buf = t & 1;
        if (t + 1 < NT) fill_tile(buf ^ 1, nbase + (t + 1) * 64);

        uint32_t* Kp = KpB + buf * 64 * 28;
        uint32_t* Vp = VpB + buf * 48 * 36;
        uint32_t* Bs = BsB + buf * 128 * 33;

        // ---- S = QK^T + bias : C init from Bs, bf16 MMA ----
        float cS[8][4];
#pragma unroll
        for (int nb = 0; nb < 8; nb++) {
            float2 bA = unpackbf(Bs[qrow * 33 + nb * 4 + tig]);
            float2 bB = unpackbf(Bs[(qrow + 8) * 33 + nb * 4 + tig]);
            cS[nb][0] = bA.x; cS[nb][1] = bA.y;
            cS[nb][2] = bB.x; cS[nb][3] = bB.y;
        }
#pragma unroll
        for (int kb = 0; kb < 3; kb++) {
            uint32_t a0 = Qp[qrow * 28 + kb * 8 + tig];
            uint32_t a1 = Qp[(qrow + 8) * 28 + kb * 8 + tig];
            uint32_t a2 = Qp[qrow * 28 + kb * 8 + tig + 4];
            uint32_t a3 = Qp[(qrow + 8) * 28 + kb * 8 + tig + 4];
#pragma unroll
            for (int nb = 0; nb < 8; nb++) {
                uint32_t b0 = Kp[(nb * 8 + gid) * 28 + kb * 8 + tig];
                uint32_t b1 = Kp[(nb * 8 + gid) * 28 + kb * 8 + tig + 4];
                mma_bf16(cS[nb], a0, a1, a2, a3, b0, b1);
            }
        }

        // ---- online softmax ----
        float tmax0 = -1e30f, tmax1 = -1e30f;
#pragma unroll
        for (int nb = 0; nb < 8; nb++) {
            tmax0 = fmaxf(tmax0, fmaxf(cS[nb][0], cS[nb][1]));
            tmax1 = fmaxf(tmax1, fmaxf(cS[nb][2], cS[nb][3]));
        }
        tmax0 = fmaxf(tmax0, __shfl_xor_sync(0xffffffffu, tmax0, 1));
        tmax0 = fmaxf(tmax0, __shfl_xor_sync(0xffffffffu, tmax0, 2));
        tmax1 = fmaxf(tmax1, __shfl_xor_sync(0xffffffffu, tmax1, 1));
        tmax1 = fmaxf(tmax1, __shfl_xor_sync(0xffffffffu, tmax1, 2));
        float nmax0 = fmaxf(rmax0, tmax0);
        float nmax1 = fmaxf(rmax1, tmax1);
        float f0 = __expf(rmax0 - nmax0);
        float f1 = __expf(rmax1 - nmax1);
        rmax0 = nmax0; rmax1 = nmax1;

        float psum0 = 0.f, psum1 = 0.f;
#pragma unroll
        for (int nb = 0; nb < 8; nb++) {
            float p0 = __expf(cS[nb][0] - nmax0);
            float p1 = __expf(cS[nb][1] - nmax0);
            float p2 = __expf(cS[nb][2] - nmax1);
            float p3 = __expf(cS[nb][3] - nmax1);
            psum0 += p0 + p1;
            psum1 += p2 + p3;
            Pp[qrow * 36 + nb * 4 + tig]       = packbf(p0, p1);
            Pp[(qrow + 8) * 36 + nb * 4 + tig] = packbf(p2, p3);
        }
        psum0 += __shfl_xor_sync(0xffffffffu, psum0, 1);
        psum0 += __shfl_xor_sync(0xffffffffu, psum0, 2);
        psum1 += __shfl_xor_sync(0xffffffffu, psum1, 1);
        psum1 += __shfl_xor_sync(0xffffffffu, psum1, 2);
        rsum0 = rsum0 * f0 + psum0;
        rsum1 = rsum1 * f1 + psum1;

#pragma unroll
        for (int nb = 0; nb < 6; nb++) {
            o[nb][0] *= f0; o[nb][1] *= f0;
            o[nb][2] *= f1; o[nb][3] *= f1;
        }
        __syncwarp();

        // ---- PV: O += P x V (bf16 m16n8k16) ----
#pragma unroll
        for (int kb = 0; kb < 4; kb++) {
            uint32_t a0 = Pp[qrow * 36 + kb * 8 + tig];
            uint32_t a1 = Pp[(qrow + 8) * 36 + kb * 8 + tig];
            uint32_t a2 = Pp[qrow * 36 + kb * 8 + tig + 4];
            uint32_t a3 = Pp[(qrow + 8) * 36 + kb * 8 + tig + 4];
#pragma unroll
            for (int nb = 0; nb < 6; nb++) {
                uint32_t b0 = Vp[(nb * 8 + gid) * 36 + kb * 8 + tig];
                uint32_t b1 = Vp[(nb * 8 + gid) * 36 + kb * 8 + tig + 4];
                mma_bf16(o[nb], a0, a1, a2, a3, b0, b1);
            }
        }
        cp_wait_all();     // prefetched K/V for next tile landed
        __syncthreads();   // all fills visible; buffers swappable
    }

    const int mA = m0 + qrow;
    const int mB = mA + 8;
    float* op = g_opart + (split * BB + b) * CC * NN;
#pragma unroll
    for (int nb = 0; nb < 6; nb++) {
        int ch = nb * 8 + 2 * tig;
        op[ch * NN + mA]       = o[nb][0];
        op[(ch + 1) * NN + mA] = o[nb][1];
        op[ch * NN + mB]       = o[nb][2];
        op[(ch + 1) * NN + mB] = o[nb][3];
    }
    if (tig == 0) {
        g_mpart[(split * BB + b) * NN + mA] = rmax0;
        g_mpart[(split * BB + b) * NN + mB] = rmax1;
        g_lpart[(split * BB + b) * NN + mA] = rsum0;
        g_lpart[(split * BB + b) * NN + mB] = rsum1;
    }
}

// ---------------- window attention: 4 windows per 256-thread block --------------
__global__ void __launch_bounds__(256, 4) winattn_kernel() {
    int b  = blockIdx.z;
    int sp = blockIdx.y;
    int wg = threadIdx.x >> 6;
    int w  = blockIdx.x * 4 + wg;
    int t  = threadIdx.x & 63;

    __shared__ float qsm[4][64][17];
    __shared__ float vsm[4][64][17];

    int py, px;
    if (sp == 0)      { int wy = w >> 3, wx = w & 7; py = wy * 8 + (t >> 3); px = wx * 8 + (t & 7); }
    else if (sp == 1) { py = t;  px = w; }
    else              { py = w;  px = t; }
    int pix = py * 64 + px;

    int qbase = (b * 96 + sp * 32) * NN + pix;
#pragma unroll
    for (int c = 0; c < 16; c++) {
        qsm[wg][t][c] = g_x2[qbase + c * NN];
        vsm[wg][t][c] = g_x2[qbase + (16 + c) * NN];
    }
    __syncthreads();

    float qr[16];
#pragma unroll
    for (int c = 0; c < 16; c++) qr[c] = qsm[wg][t][c];

    float lg[64];
    float mx = -1e30f;
    for (int j = 0; j < 64; j++) {
        float d = 0.f;
#pragma unroll
        for (int c = 0; c < 16; c++) d += qr[c] * qsm[wg][j][c];
        lg[j] = d;
        mx = fmaxf(mx, d);
    }
    float s = 0.f;
    for (int j = 0; j < 64; j++) { lg[j] = __expf(lg[j] - mx); s += lg[j]; }
    float inv = 1.f / s;

    float o[16];
#pragma unroll
    for (int c = 0; c < 16; c++) o[c] = 0.f;
    for (int j = 0; j < 64; j++) {
        float p = lg[j] * inv;
#pragma unroll
        for (int c = 0; c < 16; c++) o[c] += p * vsm[wg][j][c];
    }
#pragma unroll
    for (int c = 0; c < 16; c++)
        g_win[(b * CC + sp * 16 + c) * NN + pix] = o[c];
}

// ---------------- final: MMA pout conv + split merge + average -------------------
__global__ void __launch_bounds__(256, 2) final_kernel(
    const float* __restrict__ pw, const float* __restrict__ pb,
    float* __restrict__ out) {
    __shared__ ConvSmem S;
    const int tid = threadIdx.x;
    const int b   = blockIdx.y;
    const int m0  = blockIdx.x * 128;

    if (tid < 48) { S.sc_s[tid] = 1.f; S.bias_s[tid] = pb[tid]; }
    __syncthreads();
    conv_fill(S, g_win + b * CC * NN, m0, pw, tid);
    __syncthreads();

    const int warp = tid >> 5, lane = tid & 31;
    const int gid = lane >> 2, tig = lane & 3;
    const int qrow = warp * 16 + gid;
    float cS[6][4];
    conv_mma(S, cS, qrow, tig, gid);

    const int mA = m0 + qrow;
    const int mB = mA + 8;

    float eA[NSPLIT], eB[NSPLIT];
    {
        float MA = -1e30f, MB = -1e30f;
        float mvA[NSPLIT], mvB[NSPLIT];
#pragma unroll
        for (int s = 0; s < NSPLIT; s++) {
            mvA[s] = g_mpart[(s * BB + b) * NN + mA];
            mvB[s] = g_mpart[(s * BB + b) * NN + mB];
            MA = fmaxf(MA, mvA[s]); MB = fmaxf(MB, mvB[s]);
        }
        float lA = 0.f, lB = 0.f;
#pragma unroll
        for (int s = 0; s < NSPLIT; s++) {
            eA[s] = __expf(mvA[s] - MA);
            eB[s] = __expf(mvB[s] - MB);
            lA += g_lpart[(s * BB + b) * NN + mA] * eA[s];
            lB += g_lpart[(s * BB + b) * NN + mB] * eB[s];
        }
        float ilA = 0.5f / lA, ilB = 0.5f / lB;
#pragma unroll
        for (int s = 0; s < NSPLIT; s++) { eA[s] *= ilA; eB[s] *= ilB; }
    }

#pragma unroll
    for (int nb = 0; nb < 6; nb++) {
        int col = nb * 8 + 2 * tig;
#pragma unroll
        for (int j = 0; j < 2; j++) {
            int ch = col + j;
            float odA = 0.f, odB = 0.f;
#pragma unroll
            for (int s = 0; s < NSPLIT; s++) {
                odA += g_opart[((s * BB + b) * CC + ch) * NN + mA] * eA[s];
                odB += g_opart[((s * BB + b) * CC + ch) * NN + mB] * eB[s];
            }
            out[(b * CC + ch) * NN + mA] = 0.5f * cS[nb][j]     + odA;
            out[(b * CC + ch) * NN + mB] = 0.5f * cS[nb][2 + j] + odB;
        }
    }
}

// ---------------- launch ---------------------------------------------------------
extern "C" void kernel_launch(void* const* d_in, const int* in_sizes, int n_in,
                              void* d_out, int out_size) {
    const float* x        = (const float*)d_in[0];
    const float* Wq       = (const float*)d_in[1];
    const float* bq       = (const float*)d_in[2];
    const float* off_dw_w = (const float*)d_in[3];
    const float* off_dw_b = (const float*)d_in[4];
    const float* off_ln_g = (const float*)d_in[5];
    const float* off_ln_b = (const float*)d_in[6];
    const float* off_pw_w = (const float*)d_in[7];
    const float* Wk       = (const float*)d_in[8];
    const float* bk       = (const float*)d_in[9];
    const float* Wv       = (const float*)d_in[10];
    const float* bv       = (const float*)d_in[11];
    const float* inp_w    = (const float*)d_in[12];
    const float* inp_b    = (const float*)d_in[13];
    const float* bn_g     = (const float*)d_in[14];
    const float* bn_b     = (const float*)d_in[15];
    const float* bn_mean  = (const float*)d_in[16];
    const float* bn_var   = (const float*)d_in[17];
    const float* pout_w   = (const float*)d_in[18];
    const float* pout_b   = (const float*)d_in[19];
    const float* rpe      = (const float*)d_in[20];
    float* out = (float*)d_out;

    cudaFuncSetAttribute(attn_kernel, cudaFuncAttributeMaxDynamicSharedMemorySize,
                         ATTN_SMEM_BYTES);

    stage1_kernel<<<dim3(32, 7), 256>>>(x, Wq, bq, inp_w, inp_b,
                                        bn_g, bn_b, bn_mean, bn_var, rpe);
    deform_kernel<<<dim3(HH, BB), 512>>>(x, off_dw_w, off_dw_b,
                                         off_ln_g, off_ln_b, off_pw_w);
    stage2_kernel<<<dim3(32, 4), 256>>>(Wk, bk, Wv, bv);
    attn_kernel<<<dim3(NN / 128, NSPLIT, BB), 256, ATTN_SMEM_BYTES>>>();
    winattn_kernel<<<dim3(16, 3, BB), 256>>>();
    final_kernel<<<dim3(32, BB), 256>>>(pout_w, pout_b, out);
}